// round 3
// baseline (speedup 1.0000x reference)
#include <cuda_runtime.h>
#include <cstdint>
#include <float.h>

// Problem constants (B, H fixed by the dataset; N taken from in_sizes)
#define NGRAPH 1024
#define HDIM   64

// ---------------- device scratch (no allocation allowed) ----------------
__device__ float4 d_WL[32 * 256];    // packed LSTM weights: K=128 (h-part folded), [k4][n]
__device__ float  d_bsum[256];       // b_ih + b_hh
__device__ float4 d_W1p[32 * 256];   // W1 packed [k4][n], K=128, Nout=256
__device__ float4 d_W2p[64 * 128];   // W2 packed [k4][n], K=256, Nout=128
__device__ int    d_seg[NGRAPH + 1]; // segment row offsets

// ---------------- segment offsets from sorted int32 batch ----------------
// (reference uses jnp.int64 but JAX x64 is disabled -> actual dtype is int32)
__global__ void seg_kernel(const int* __restrict__ batch, int n) {
    int i = blockIdx.x * blockDim.x + threadIdx.x;
    if (i >= n) return;
    int b  = batch[i];
    b = min(max(b, 0), NGRAPH - 1);
    int bp;
    if (i == 0) bp = -1;
    else {
        bp = batch[i - 1];
        bp = min(max(bp, 0), NGRAPH - 1);
    }
    for (int v = bp + 1; v <= b; v++) d_seg[v] = i;
    if (i == n - 1) {
        for (int v = b + 1; v <= NGRAPH; v++) d_seg[v] = n;
    }
}

// ---------------- weight packing ----------------
// gates = h @ (W_ih[:, :64] + W_hh).T + r @ W_ih[:, 64:].T + (b_ih + b_hh)
// (valid because q_star = [q, r] with q == h)
__global__ void pack_kernel(const float* __restrict__ Wih, const float* __restrict__ Whh,
                            const float* __restrict__ bih, const float* __restrict__ bhh,
                            const float* __restrict__ W1,  const float* __restrict__ W2) {
    int t = blockIdx.x * blockDim.x + threadIdx.x;   // 0 .. 8191
    if (t < 32 * 256) {
        int k4 = t >> 8, n = t & 255;
        float4 w;
        float* wp = (float*)&w;
        #pragma unroll
        for (int j = 0; j < 4; j++) {
            int k = k4 * 4 + j;
            if (k < 64) wp[j] = Wih[n * 128 + k] + Whh[n * 64 + k];
            else        wp[j] = Wih[n * 128 + k];   // k in [64,128): r-part
        }
        d_WL[t] = w;
    }
    if (t < 256) d_bsum[t] = bih[t] + bhh[t];
    if (t < 32 * 256) {
        int k4 = t >> 8, n = t & 255;
        float4 w; float* wp = (float*)&w;
        #pragma unroll
        for (int j = 0; j < 4; j++) wp[j] = W1[n * 128 + k4 * 4 + j];
        d_W1p[t] = w;
    }
    if (t < 64 * 128) {
        int k4 = t >> 7, n = t & 127;
        float4 w; float* wp = (float*)&w;
        #pragma unroll
        for (int j = 0; j < 4; j++) wp[j] = W2[n * 256 + k4 * 4 + j];
        d_W2p[t] = w;
    }
}

__device__ __forceinline__ float sigmoidf_(float v) {
    return 1.0f / (1.0f + __expf(-v));
}

// ---------------- fused Set2Set + MLP: 256 CTAs x 4 graphs, 512 threads ----------------
__global__ __launch_bounds__(512, 2)
void fused_kernel(const float* __restrict__ x,
                  const float* __restrict__ b1,
                  const float* __restrict__ b2,
                  float* __restrict__ out, int n) {
    __shared__ float s_act[4][128];   // per graph: [h(64) | r(64)]  (== q_star order [q, r])
    __shared__ float s_c[4][64];
    __shared__ float s_g[4][256];     // gates; s_g[0] reused as MLP hidden
    __shared__ float s_rm[32], s_rs[32];
    __shared__ float s_rR[32][64];

    const int t = threadIdx.x;
    const int c = blockIdx.x;         // graphs 4c .. 4c+3
    const int hw = t >> 4;            // half-warp id 0..31
    const int hl = t & 15;            // lane within half-warp
    const unsigned hmask = 0xFFFFu << (t & 16);   // mask for this half-warp only

    if (t < 128) {
        #pragma unroll
        for (int g = 0; g < 4; g++) {
            s_act[g][t] = 0.0f;
            if (t < 64) s_c[g][t] = 0.0f;
        }
    }
    int row0[4], row1[4];
    #pragma unroll
    for (int g = 0; g < 4; g++) {
        int a = d_seg[4 * c + g];
        int b = d_seg[4 * c + g + 1];
        a = min(max(a, 0), n);
        b = min(max(b, a), n);
        row0[g] = a;
        row1[g] = b;
    }
    __syncthreads();

    for (int step = 0; step < 5; step++) {
        // ---- LSTM gates: 512 threads = 256 gates x 2 graph-pairs ----
        {
            const int nn = t & 255;
            const int gp = t >> 8;                   // 0/1 -> graphs {2gp, 2gp+1}
            float acc0 = d_bsum[nn];
            float acc1 = acc0;
            const float4* a0 = (const float4*)s_act[2 * gp];
            const float4* a1 = (const float4*)s_act[2 * gp + 1];
            #pragma unroll 8
            for (int k4 = 0; k4 < 32; k4++) {
                float4 w  = d_WL[k4 * 256 + nn];
                float4 v0 = a0[k4];
                float4 v1 = a1[k4];
                acc0 += w.x * v0.x + w.y * v0.y + w.z * v0.z + w.w * v0.w;
                acc1 += w.x * v1.x + w.y * v1.y + w.z * v1.z + w.w * v1.w;
            }
            s_g[2 * gp][nn]     = acc0;
            s_g[2 * gp + 1][nn] = acc1;
        }
        __syncthreads();
        if (t < 256) {
            const int g = t >> 6, k = t & 63;
            float gi = sigmoidf_(s_g[g][k]);
            float gf = sigmoidf_(s_g[g][64 + k]);
            float gg = tanhf(s_g[g][128 + k]);
            float go = sigmoidf_(s_g[g][192 + k]);
            float cc = gf * s_c[g][k] + gi * gg;
            s_c[g][k] = cc;
            s_act[g][k] = go * tanhf(cc);            // h (== q)
        }
        __syncthreads();

        // ---- attention: one streaming pass per graph, online softmax ----
        for (int g = 0; g < 4; g++) {
            const float4 q = ((const float4*)s_act[g])[hl];   // q[hl*4 .. hl*4+3]
            float m = -FLT_MAX, s = 0.0f;
            float4 R = make_float4(0.f, 0.f, 0.f, 0.f);

            int i   = row0[g] + hw;
            int end = row1[g];
            for (; i + 32 < end; i += 64) {
                float4 v0 = __ldcs((const float4*)(x + (size_t)i * 64) + hl);
                float4 v1 = __ldcs((const float4*)(x + (size_t)(i + 32) * 64) + hl);
                float p0 = v0.x * q.x + v0.y * q.y + v0.z * q.z + v0.w * q.w;
                float p1 = v1.x * q.x + v1.y * q.y + v1.z * q.z + v1.w * q.w;
                #pragma unroll
                for (int msk = 8; msk >= 1; msk >>= 1) {
                    p0 += __shfl_xor_sync(hmask, p0, msk);
                    p1 += __shfl_xor_sync(hmask, p1, msk);
                }
                if (p0 <= m) {
                    float d = __expf(p0 - m);
                    s += d;
                    R.x += d * v0.x; R.y += d * v0.y; R.z += d * v0.z; R.w += d * v0.w;
                } else {
                    float sc = __expf(m - p0);
                    s = s * sc + 1.0f;
                    R.x = R.x * sc + v0.x; R.y = R.y * sc + v0.y;
                    R.z = R.z * sc + v0.z; R.w = R.w * sc + v0.w;
                    m = p0;
                }
                if (p1 <= m) {
                    float d = __expf(p1 - m);
                    s += d;
                    R.x += d * v1.x; R.y += d * v1.y; R.z += d * v1.z; R.w += d * v1.w;
                } else {
                    float sc = __expf(m - p1);
                    s = s * sc + 1.0f;
                    R.x = R.x * sc + v1.x; R.y = R.y * sc + v1.y;
                    R.z = R.z * sc + v1.z; R.w = R.w * sc + v1.w;
                    m = p1;
                }
            }
            if (i < end) {
                float4 v0 = __ldcs((const float4*)(x + (size_t)i * 64) + hl);
                float p0 = v0.x * q.x + v0.y * q.y + v0.z * q.z + v0.w * q.w;
                #pragma unroll
                for (int msk = 8; msk >= 1; msk >>= 1)
                    p0 += __shfl_xor_sync(hmask, p0, msk);
                if (p0 <= m) {
                    float d = __expf(p0 - m);
                    s += d;
                    R.x += d * v0.x; R.y += d * v0.y; R.z += d * v0.z; R.w += d * v0.w;
                } else {
                    float sc = __expf(m - p0);
                    s = s * sc + 1.0f;
                    R.x = R.x * sc + v0.x; R.y = R.y * sc + v0.y;
                    R.z = R.z * sc + v0.z; R.w = R.w * sc + v0.w;
                    m = p0;
                }
            }

            // combine 32 half-warp partials
            if (hl == 0) { s_rm[hw] = m; s_rs[hw] = s; }
            ((float4*)s_rR[hw])[hl] = R;
            __syncthreads();
            if (t < 64) {
                float M = -FLT_MAX;
                #pragma unroll 8
                for (int p = 0; p < 32; p++) M = fmaxf(M, s_rm[p]);
                float st = 0.0f, Rk = 0.0f;
                #pragma unroll 8
                for (int p = 0; p < 32; p++) {
                    float w = __expf(s_rm[p] - M);
                    st += w * s_rs[p];
                    Rk += w * s_rR[p][t];
                }
                s_act[g][64 + t] = Rk / fmaxf(st, 1e-16f);   // r
            }
            __syncthreads();
        }
    }

    // ---- final MLP per graph: 128 -> 256 (relu) -> 128 ----
    for (int g = 0; g < 4; g++) {
        if (t < 256) {
            float acc = b1[t];
            const float4* a = (const float4*)s_act[g];
            #pragma unroll 8
            for (int k4 = 0; k4 < 32; k4++) {
                float4 w = d_W1p[k4 * 256 + t];
                float4 v = a[k4];
                acc += w.x * v.x + w.y * v.y + w.z * v.z + w.w * v.w;
            }
            s_g[0][t] = fmaxf(acc, 0.0f);
        }
        __syncthreads();
        if (t < 128) {
            float acc = b2[t];
            const float4* hv = (const float4*)s_g[0];
            #pragma unroll 8
            for (int k4 = 0; k4 < 64; k4++) {
                float4 w = d_W2p[k4 * 128 + t];
                float4 v = hv[k4];
                acc += w.x * v.x + w.y * v.y + w.z * v.z + w.w * v.w;
            }
            out[(size_t)(4 * c + g) * 128 + t] = acc;
        }
        __syncthreads();
    }
}

extern "C" void kernel_launch(void* const* d_in, const int* in_sizes, int n_in,
                              void* d_out, int out_size) {
    const float* x     = (const float*)d_in[0];
    const int*   batch = (const int*)d_in[1];     // int32 (JAX x64 disabled)
    const float* Wih   = (const float*)d_in[2];
    const float* Whh   = (const float*)d_in[3];
    const float* bih   = (const float*)d_in[4];
    const float* bhh   = (const float*)d_in[5];
    const float* W1    = (const float*)d_in[6];
    const float* b1    = (const float*)d_in[7];
    const float* W2    = (const float*)d_in[8];
    const float* b2    = (const float*)d_in[9];

    int n = in_sizes[0] / HDIM;   // number of nodes

    seg_kernel<<<(n + 511) / 512, 512>>>(batch, n);
    pack_kernel<<<16, 512>>>(Wih, Whh, bih, bhh, W1, W2);
    fused_kernel<<<256, 512>>>(x, b1, b2, (float*)d_out, n);
}

// round 4
// speedup vs baseline: 1.1542x; 1.1542x over previous
#include <cuda_runtime.h>
#include <cuda_fp16.h>
#include <cstdint>
#include <float.h>

// Problem constants (B, H fixed by the dataset; N taken from in_sizes)
#define NGRAPH 1024
#define HDIM   64
#define NMAX   1000000

// ---------------- device scratch (no allocation allowed) ----------------
__device__ float4 d_WL[32 * 256];    // packed LSTM weights: K=128 (h-part folded), [k4][n]
__device__ float  d_bsum[256];       // b_ih + b_hh
__device__ float4 d_W1p[32 * 256];   // W1 packed [k4][n], K=128, Nout=256
__device__ float4 d_W2p[64 * 128];   // W2 packed [k4][n], K=256, Nout=128
__device__ int    d_seg[NGRAPH + 1]; // segment row offsets
__device__ uint4  d_xh[NMAX * 8];    // fp16 copy of x: row = 64 halves = 8 uint4

// ---------------- segment offsets from sorted int32 batch ----------------
// (reference uses jnp.int64 but JAX x64 is disabled -> actual dtype is int32)
__global__ void seg_kernel(const int* __restrict__ batch, int n) {
    int i = blockIdx.x * blockDim.x + threadIdx.x;
    if (i >= n) return;
    int b  = batch[i];
    b = min(max(b, 0), NGRAPH - 1);
    int bp;
    if (i == 0) bp = -1;
    else {
        bp = batch[i - 1];
        bp = min(max(bp, 0), NGRAPH - 1);
    }
    for (int v = bp + 1; v <= b; v++) d_seg[v] = i;
    if (i == n - 1) {
        for (int v = b + 1; v <= NGRAPH; v++) d_seg[v] = n;
    }
}

// ---------------- weight packing ----------------
// gates = h @ (W_ih[:, :64] + W_hh).T + r @ W_ih[:, 64:].T + (b_ih + b_hh)
// (valid because q_star = [q, r] with q == h)
__global__ void pack_kernel(const float* __restrict__ Wih, const float* __restrict__ Whh,
                            const float* __restrict__ bih, const float* __restrict__ bhh,
                            const float* __restrict__ W1,  const float* __restrict__ W2) {
    int t = blockIdx.x * blockDim.x + threadIdx.x;   // 0 .. 8191
    if (t < 32 * 256) {
        int k4 = t >> 8, n = t & 255;
        float4 w;
        float* wp = (float*)&w;
        #pragma unroll
        for (int j = 0; j < 4; j++) {
            int k = k4 * 4 + j;
            if (k < 64) wp[j] = Wih[n * 128 + k] + Whh[n * 64 + k];
            else        wp[j] = Wih[n * 128 + k];   // k in [64,128): r-part
        }
        d_WL[t] = w;
    }
    if (t < 256) d_bsum[t] = bih[t] + bhh[t];
    if (t < 32 * 256) {
        int k4 = t >> 8, n = t & 255;
        float4 w; float* wp = (float*)&w;
        #pragma unroll
        for (int j = 0; j < 4; j++) wp[j] = W1[n * 128 + k4 * 4 + j];
        d_W1p[t] = w;
    }
    if (t < 64 * 128) {
        int k4 = t >> 7, n = t & 127;
        float4 w; float* wp = (float*)&w;
        #pragma unroll
        for (int j = 0; j < 4; j++) wp[j] = W2[n * 256 + k4 * 4 + j];
        d_W2p[t] = w;
    }
}

__device__ __forceinline__ float sigmoidf_(float v) {
    return 1.0f / (1.0f + __expf(-v));
}

// online-softmax accumulator update (p is the row logit, va/vb the 8 owned cols)
__device__ __forceinline__ void os_update(float& m, float& s, float4& Ra, float4& Rb,
                                          float p, const float4& va, const float4& vb) {
    if (p <= m) {
        float d = __expf(p - m);
        s += d;
        Ra.x += d * va.x; Ra.y += d * va.y; Ra.z += d * va.z; Ra.w += d * va.w;
        Rb.x += d * vb.x; Rb.y += d * vb.y; Rb.z += d * vb.z; Rb.w += d * vb.w;
    } else {
        float sc = __expf(m - p);
        s = s * sc + 1.0f;
        Ra.x = Ra.x * sc + va.x; Ra.y = Ra.y * sc + va.y;
        Ra.z = Ra.z * sc + va.z; Ra.w = Ra.w * sc + va.w;
        Rb.x = Rb.x * sc + vb.x; Rb.y = Rb.y * sc + vb.y;
        Rb.z = Rb.z * sc + vb.z; Rb.w = Rb.w * sc + vb.w;
        m = p;
    }
}

// fp32 row body (step 0): read x, dot, convert+store fp16 copy
__device__ __forceinline__ void body_f32(const float* __restrict__ x, int i, int ol,
                                         unsigned omask,
                                         const float4& qa, const float4& qb,
                                         float& m, float& s, float4& Ra, float4& Rb) {
    const float4* rp = (const float4*)(x + (size_t)i * 64);
    float4 va = __ldcs(rp + 2 * ol);
    float4 vb = __ldcs(rp + 2 * ol + 1);
    float p = va.x * qa.x + va.y * qa.y + va.z * qa.z + va.w * qa.w
            + vb.x * qb.x + vb.y * qb.y + vb.z * qb.z + vb.w * qb.w;
    #pragma unroll
    for (int msk = 4; msk >= 1; msk >>= 1)
        p += __shfl_xor_sync(omask, p, msk);
    union { uint4 u; __half2 h[4]; } pk;
    pk.h[0] = __floats2half2_rn(va.x, va.y);
    pk.h[1] = __floats2half2_rn(va.z, va.w);
    pk.h[2] = __floats2half2_rn(vb.x, vb.y);
    pk.h[3] = __floats2half2_rn(vb.z, vb.w);
    __stcs(&d_xh[(size_t)i * 8 + ol], pk.u);
    os_update(m, s, Ra, Rb, p, va, vb);
}

// fp16 row body (steps 1-4): read fp16 copy
__device__ __forceinline__ void body_f16(int i, int ol, unsigned omask,
                                         const float4& qa, const float4& qb,
                                         float& m, float& s, float4& Ra, float4& Rb) {
    union { uint4 u; __half2 h[4]; } pk;
    pk.u = d_xh[(size_t)i * 8 + ol];
    float2 f0 = __half22float2(pk.h[0]);
    float2 f1 = __half22float2(pk.h[1]);
    float2 f2 = __half22float2(pk.h[2]);
    float2 f3 = __half22float2(pk.h[3]);
    float4 va = make_float4(f0.x, f0.y, f1.x, f1.y);
    float4 vb = make_float4(f2.x, f2.y, f3.x, f3.y);
    float p = va.x * qa.x + va.y * qa.y + va.z * qa.z + va.w * qa.w
            + vb.x * qb.x + vb.y * qb.y + vb.z * qb.z + vb.w * qb.w;
    #pragma unroll
    for (int msk = 4; msk >= 1; msk >>= 1)
        p += __shfl_xor_sync(omask, p, msk);
    os_update(m, s, Ra, Rb, p, va, vb);
}

// ---------------- fused Set2Set + MLP: 512 CTAs x 2 graphs, 256 threads ----------------
__global__ __launch_bounds__(256, 4)
void fused_kernel(const float* __restrict__ x,
                  const float* __restrict__ b1,
                  const float* __restrict__ b2,
                  float* __restrict__ out, int n) {
    __shared__ float s_act[2][128];   // per graph: [h(64) | r(64)]  (== q_star order [q, r])
    __shared__ float s_c[2][64];
    __shared__ float s_g[2][256];     // gates; s_g[0] reused as MLP hidden
    __shared__ float s_rm[32], s_rs[32];
    __shared__ float s_rR[32][64];

    const int t  = threadIdx.x;
    const int c  = blockIdx.x;        // graphs 2c, 2c+1
    const int oct = t >> 3;           // octet id 0..31
    const int ol  = t & 7;            // lane within octet
    const unsigned omask = 0xFFu << (t & 24);   // shfl mask for this octet

    if (t < 128) {
        #pragma unroll
        for (int g = 0; g < 2; g++) {
            s_act[g][t] = 0.0f;
            if (t < 64) s_c[g][t] = 0.0f;
        }
    }
    int row0[2], row1[2];
    #pragma unroll
    for (int g = 0; g < 2; g++) {
        int a = d_seg[2 * c + g];
        int b = d_seg[2 * c + g + 1];
        a = min(max(a, 0), n);
        b = min(max(b, a), n);
        row0[g] = a;
        row1[g] = b;
    }
    __syncthreads();

    for (int step = 0; step < 5; step++) {
        // ---- LSTM gates: 256 threads = 256 gates, both graphs per thread ----
        {
            float acc0 = d_bsum[t];
            float acc1 = acc0;
            const float4* a0 = (const float4*)s_act[0];
            const float4* a1 = (const float4*)s_act[1];
            #pragma unroll 8
            for (int k4 = 0; k4 < 32; k4++) {
                float4 w  = d_WL[k4 * 256 + t];
                float4 v0 = a0[k4];
                float4 v1 = a1[k4];
                acc0 += w.x * v0.x + w.y * v0.y + w.z * v0.z + w.w * v0.w;
                acc1 += w.x * v1.x + w.y * v1.y + w.z * v1.z + w.w * v1.w;
            }
            s_g[0][t] = acc0;
            s_g[1][t] = acc1;
        }
        __syncthreads();
        if (t < 128) {
            const int g = t >> 6, k = t & 63;
            float gi = sigmoidf_(s_g[g][k]);
            float gf = sigmoidf_(s_g[g][64 + k]);
            float gg = tanhf(s_g[g][128 + k]);
            float go = sigmoidf_(s_g[g][192 + k]);
            float cc = gf * s_c[g][k] + gi * gg;
            s_c[g][k] = cc;
            s_act[g][k] = go * tanhf(cc);            // h (== q)
        }
        __syncthreads();

        // ---- attention: one streaming pass per graph, online softmax ----
        for (int g = 0; g < 2; g++) {
            const float4 qa = ((const float4*)s_act[g])[2 * ol];
            const float4 qb = ((const float4*)s_act[g])[2 * ol + 1];
            float m = -FLT_MAX, s = 0.0f;
            float4 Ra = make_float4(0.f, 0.f, 0.f, 0.f);
            float4 Rb = make_float4(0.f, 0.f, 0.f, 0.f);

            int i   = row0[g] + oct;
            int end = row1[g];
            if (step == 0) {
                for (; i + 32 < end; i += 64) {
                    body_f32(x, i,      ol, omask, qa, qb, m, s, Ra, Rb);
                    body_f32(x, i + 32, ol, omask, qa, qb, m, s, Ra, Rb);
                }
                if (i < end)
                    body_f32(x, i, ol, omask, qa, qb, m, s, Ra, Rb);
            } else {
                for (; i + 32 < end; i += 64) {
                    body_f16(i,      ol, omask, qa, qb, m, s, Ra, Rb);
                    body_f16(i + 32, ol, omask, qa, qb, m, s, Ra, Rb);
                }
                if (i < end)
                    body_f16(i, ol, omask, qa, qb, m, s, Ra, Rb);
            }

            // combine 32 octet partials
            if (ol == 0) { s_rm[oct] = m; s_rs[oct] = s; }
            ((float4*)s_rR[oct])[2 * ol]     = Ra;
            ((float4*)s_rR[oct])[2 * ol + 1] = Rb;
            __syncthreads();
            if (t < 64) {
                float M = -FLT_MAX;
                #pragma unroll 8
                for (int p = 0; p < 32; p++) M = fmaxf(M, s_rm[p]);
                float st = 0.0f, Rk = 0.0f;
                #pragma unroll 8
                for (int p = 0; p < 32; p++) {
                    float w = __expf(s_rm[p] - M);
                    st += w * s_rs[p];
                    Rk += w * s_rR[p][t];
                }
                s_act[g][64 + t] = Rk / fmaxf(st, 1e-16f);   // r
            }
            __syncthreads();
        }
    }

    // ---- final MLP per graph: 128 -> 256 (relu) -> 128 ----
    for (int g = 0; g < 2; g++) {
        {
            float acc = b1[t];
            const float4* a = (const float4*)s_act[g];
            #pragma unroll 8
            for (int k4 = 0; k4 < 32; k4++) {
                float4 w = d_W1p[k4 * 256 + t];
                float4 v = a[k4];
                acc += w.x * v.x + w.y * v.y + w.z * v.z + w.w * v.w;
            }
            s_g[0][t] = fmaxf(acc, 0.0f);
        }
        __syncthreads();
        if (t < 128) {
            float acc = b2[t];
            const float4* hv = (const float4*)s_g[0];
            #pragma unroll 8
            for (int k4 = 0; k4 < 64; k4++) {
                float4 w = d_W2p[k4 * 128 + t];
                float4 v = hv[k4];
                acc += w.x * v.x + w.y * v.y + w.z * v.z + w.w * v.w;
            }
            out[(size_t)(2 * c + g) * 128 + t] = acc;
        }
        __syncthreads();
    }
}

extern "C" void kernel_launch(void* const* d_in, const int* in_sizes, int n_in,
                              void* d_out, int out_size) {
    const float* x     = (const float*)d_in[0];
    const int*   batch = (const int*)d_in[1];     // int32 (JAX x64 disabled)
    const float* Wih   = (const float*)d_in[2];
    const float* Whh   = (const float*)d_in[3];
    const float* bih   = (const float*)d_in[4];
    const float* bhh   = (const float*)d_in[5];
    const float* W1    = (const float*)d_in[6];
    const float* b1    = (const float*)d_in[7];
    const float* W2    = (const float*)d_in[8];
    const float* b2    = (const float*)d_in[9];

    int n = in_sizes[0] / HDIM;   // number of nodes

    seg_kernel<<<(n + 511) / 512, 512>>>(batch, n);
    pack_kernel<<<16, 512>>>(Wih, Whh, bih, bhh, W1, W2);
    fused_kernel<<<512, 256>>>(x, b1, b2, (float*)d_out, n);
}

// round 5
// speedup vs baseline: 1.2105x; 1.0488x over previous
#include <cuda_runtime.h>
#include <cuda_fp16.h>
#include <cstdint>
#include <float.h>

#define NGRAPH 1024
#define HDIM   64
#define NMAX   1000000
#define CTAS   296        // 2 x 148 SMs -> exactly one balanced wave at occ 2

// ---------------- device scratch (no allocation allowed) ----------------
__device__ float4 d_WL[32 * 256];    // packed LSTM weights: K=128 (h folded), [k4][n]
__device__ float  d_bsum[256];       // b_ih + b_hh
__device__ float4 d_W1p[32 * 256];   // W1 packed [k4][n]
__device__ float4 d_W2p[64 * 128];   // W2 packed [k4][n]
__device__ int    d_seg[NGRAPH + 1]; // segment row offsets
__device__ uint4  d_xh[NMAX * 8];    // fp16 copy of x (row = 64 halves = 8 uint4)

// ---------------- segment offsets from sorted int32 batch ----------------
__global__ void seg_kernel(const int* __restrict__ batch, int n) {
    int i = blockIdx.x * blockDim.x + threadIdx.x;
    if (i >= n) return;
    int b = batch[i];
    b = min(max(b, 0), NGRAPH - 1);
    int bp;
    if (i == 0) bp = -1;
    else {
        bp = batch[i - 1];
        bp = min(max(bp, 0), NGRAPH - 1);
    }
    for (int v = bp + 1; v <= b; v++) d_seg[v] = i;
    if (i == n - 1) {
        for (int v = b + 1; v <= NGRAPH; v++) d_seg[v] = n;
    }
}

// ---------------- weight packing ----------------
// gates = h @ (W_ih[:, :64] + W_hh).T + r @ W_ih[:, 64:].T + (b_ih + b_hh)
__global__ void pack_kernel(const float* __restrict__ Wih, const float* __restrict__ Whh,
                            const float* __restrict__ bih, const float* __restrict__ bhh,
                            const float* __restrict__ W1,  const float* __restrict__ W2) {
    int t = blockIdx.x * blockDim.x + threadIdx.x;   // 0 .. 8191
    if (t < 32 * 256) {
        int k4 = t >> 8, n = t & 255;
        float4 w; float* wp = (float*)&w;
        #pragma unroll
        for (int j = 0; j < 4; j++) {
            int k = k4 * 4 + j;
            if (k < 64) wp[j] = Wih[n * 128 + k] + Whh[n * 64 + k];
            else        wp[j] = Wih[n * 128 + k];
        }
        d_WL[t] = w;
    }
    if (t < 256) d_bsum[t] = bih[t] + bhh[t];
    if (t < 32 * 256) {
        int k4 = t >> 8, n = t & 255;
        float4 w; float* wp = (float*)&w;
        #pragma unroll
        for (int j = 0; j < 4; j++) wp[j] = W1[n * 128 + k4 * 4 + j];
        d_W1p[t] = w;
    }
    if (t < 64 * 128) {
        int k4 = t >> 7, n = t & 127;
        float4 w; float* wp = (float*)&w;
        #pragma unroll
        for (int j = 0; j < 4; j++) wp[j] = W2[n * 256 + k4 * 4 + j];
        d_W2p[t] = w;
    }
}

__device__ __forceinline__ float sigmoidf_(float v) {
    return 1.0f / (1.0f + __expf(-v));
}

// load row i (fp32 x), convert + store fp16 copy
__device__ __forceinline__ void load_row_f32(const float* __restrict__ x, int i, int ol,
                                             float4& va, float4& vb) {
    const float4* rp = (const float4*)(x + (size_t)i * 64);
    va = __ldcs(rp + 2 * ol);
    vb = __ldcs(rp + 2 * ol + 1);
    union { uint4 u; __half2 h[4]; } pk;
    pk.h[0] = __floats2half2_rn(va.x, va.y);
    pk.h[1] = __floats2half2_rn(va.z, va.w);
    pk.h[2] = __floats2half2_rn(vb.x, vb.y);
    pk.h[3] = __floats2half2_rn(vb.z, vb.w);
    __stcs(&d_xh[(size_t)i * 8 + ol], pk.u);
}

// load row i from fp16 copy
__device__ __forceinline__ void load_row_f16(int i, int ol, float4& va, float4& vb) {
    union { uint4 u; __half2 h[4]; } pk;
    pk.u = __ldcs(&d_xh[(size_t)i * 8 + ol]);
    float2 f0 = __half22float2(pk.h[0]);
    float2 f1 = __half22float2(pk.h[1]);
    float2 f2 = __half22float2(pk.h[2]);
    float2 f3 = __half22float2(pk.h[3]);
    va = make_float4(f0.x, f0.y, f1.x, f1.y);
    vb = make_float4(f2.x, f2.y, f3.x, f3.y);
}

__device__ __forceinline__ float rowdot(const float4& va, const float4& vb,
                                        const float4& qa, const float4& qb,
                                        unsigned omask) {
    float p = va.x * qa.x + va.y * qa.y + va.z * qa.z + va.w * qa.w
            + vb.x * qb.x + vb.y * qb.y + vb.z * qb.z + vb.w * qb.w;
    #pragma unroll
    for (int msk = 4; msk >= 1; msk >>= 1)
        p += __shfl_xor_sync(omask, p, msk);
    return p;
}

__device__ __forceinline__ void os_acc(float& s, float4& Ra, float4& Rb, float d,
                                       const float4& va, const float4& vb) {
    s += d;
    Ra.x += d * va.x; Ra.y += d * va.y; Ra.z += d * va.z; Ra.w += d * va.w;
    Rb.x += d * vb.x; Rb.y += d * vb.y; Rb.z += d * vb.z; Rb.w += d * vb.w;
}

__device__ __forceinline__ void os_update1(float& m, float& s, float4& Ra, float4& Rb,
                                           float p, const float4& va, const float4& vb) {
    if (p <= m) {
        os_acc(s, Ra, Rb, __expf(p - m), va, vb);
    } else {
        float sc = __expf(m - p);
        s *= sc;
        Ra.x *= sc; Ra.y *= sc; Ra.z *= sc; Ra.w *= sc;
        Rb.x *= sc; Rb.y *= sc; Rb.z *= sc; Rb.w *= sc;
        m = p;
        os_acc(s, Ra, Rb, 1.0f, va, vb);
    }
}

// one attention streaming pass, batch-4 rows (MLP=4), online softmax
template<bool FIRST>
__device__ __forceinline__ void attn_pass(const float* __restrict__ x,
                                          int i, int end, int ol, unsigned omask,
                                          const float4& qa, const float4& qb,
                                          float& m, float& s, float4& Ra, float4& Rb) {
    for (; i + 96 < end; i += 128) {
        float4 va0, vb0, va1, vb1, va2, vb2, va3, vb3;
        if (FIRST) {
            load_row_f32(x, i,      ol, va0, vb0);
            load_row_f32(x, i + 32, ol, va1, vb1);
            load_row_f32(x, i + 64, ol, va2, vb2);
            load_row_f32(x, i + 96, ol, va3, vb3);
        } else {
            load_row_f16(i,      ol, va0, vb0);
            load_row_f16(i + 32, ol, va1, vb1);
            load_row_f16(i + 64, ol, va2, vb2);
            load_row_f16(i + 96, ol, va3, vb3);
        }
        float p0 = rowdot(va0, vb0, qa, qb, omask);
        float p1 = rowdot(va1, vb1, qa, qb, omask);
        float p2 = rowdot(va2, vb2, qa, qb, omask);
        float p3 = rowdot(va3, vb3, qa, qb, omask);
        float P = fmaxf(fmaxf(p0, p1), fmaxf(p2, p3));
        if (P > m) {
            float sc = __expf(m - P);
            s *= sc;
            Ra.x *= sc; Ra.y *= sc; Ra.z *= sc; Ra.w *= sc;
            Rb.x *= sc; Rb.y *= sc; Rb.z *= sc; Rb.w *= sc;
            m = P;
        }
        os_acc(s, Ra, Rb, __expf(p0 - m), va0, vb0);
        os_acc(s, Ra, Rb, __expf(p1 - m), va1, vb1);
        os_acc(s, Ra, Rb, __expf(p2 - m), va2, vb2);
        os_acc(s, Ra, Rb, __expf(p3 - m), va3, vb3);
    }
    for (; i < end; i += 32) {
        float4 va, vb;
        if (FIRST) load_row_f32(x, i, ol, va, vb);
        else       load_row_f16(i, ol, va, vb);
        float p = rowdot(va, vb, qa, qb, omask);
        os_update1(m, s, Ra, Rb, p, va, vb);
    }
}

// ---------------- fused Set2Set + MLP: 296 CTAs, dynamic graph partition ----------------
__global__ __launch_bounds__(256, 2)
void fused_kernel(const float* __restrict__ x,
                  const float* __restrict__ b1,
                  const float* __restrict__ b2,
                  float* __restrict__ out, int n) {
    __shared__ float s_act[4][128];   // per graph slot: [h(64) | r(64)]
    __shared__ float s_c[4][64];
    __shared__ float s_g[4][256];     // gates; s_g[0] reused as MLP hidden
    __shared__ float s_rm[32], s_rs[32];
    __shared__ float s_rR[32][64];

    const int t   = threadIdx.x;
    const int c   = blockIdx.x;
    const int oct = t >> 3;           // octet id 0..31
    const int ol  = t & 7;            // lane within octet
    const unsigned omask = 0xFFu << (t & 24);

    const int g0  = (c * NGRAPH) / CTAS;
    const int g1  = ((c + 1) * NGRAPH) / CTAS;
    const int ngr = g1 - g0;          // 3 or 4

    if (t < 128) {
        #pragma unroll
        for (int gi = 0; gi < 4; gi++) {
            s_act[gi][t] = 0.0f;
            if (t < 64) s_c[gi][t] = 0.0f;
        }
    }
    int row0[4], row1[4];
    #pragma unroll
    for (int gi = 0; gi < 4; gi++) {
        int gg = min(g0 + gi, NGRAPH - 1);
        int a = d_seg[gg];
        int b = d_seg[gg + 1];
        a = min(max(a, 0), n);
        b = min(max(b, a), n);
        row0[gi] = a;
        row1[gi] = b;
    }
    __syncthreads();

    for (int step = 0; step < 5; step++) {
        // ---- LSTM gates: 256 threads = 256 gates, all graph slots per thread ----
        {
            float acc0 = d_bsum[t], acc1 = acc0, acc2 = acc0, acc3 = acc0;
            const float4* a0 = (const float4*)s_act[0];
            const float4* a1 = (const float4*)s_act[1];
            const float4* a2 = (const float4*)s_act[2];
            const float4* a3 = (const float4*)s_act[3];
            #pragma unroll 8
            for (int k4 = 0; k4 < 32; k4++) {
                float4 w  = d_WL[k4 * 256 + t];
                float4 v0 = a0[k4];
                float4 v1 = a1[k4];
                float4 v2 = a2[k4];
                float4 v3 = a3[k4];
                acc0 += w.x * v0.x + w.y * v0.y + w.z * v0.z + w.w * v0.w;
                acc1 += w.x * v1.x + w.y * v1.y + w.z * v1.z + w.w * v1.w;
                acc2 += w.x * v2.x + w.y * v2.y + w.z * v2.z + w.w * v2.w;
                acc3 += w.x * v3.x + w.y * v3.y + w.z * v3.z + w.w * v3.w;
            }
            s_g[0][t] = acc0;
            s_g[1][t] = acc1;
            s_g[2][t] = acc2;
            s_g[3][t] = acc3;
        }
        __syncthreads();
        {
            const int gi = t >> 6, k = t & 63;   // 4 graphs x 64 lanes = 256 threads
            float gc = sigmoidf_(s_g[gi][k]);
            float gf = sigmoidf_(s_g[gi][64 + k]);
            float gg = tanhf(s_g[gi][128 + k]);
            float go = sigmoidf_(s_g[gi][192 + k]);
            float cc = gf * s_c[gi][k] + gc * gg;
            s_c[gi][k] = cc;
            s_act[gi][k] = go * tanhf(cc);       // h (== q)
        }
        __syncthreads();

        // ---- attention per graph: single streaming pass, online softmax ----
        for (int gi = 0; gi < ngr; gi++) {
            const float4 qa = ((const float4*)s_act[gi])[2 * ol];
            const float4 qb = ((const float4*)s_act[gi])[2 * ol + 1];
            float m = -FLT_MAX, s = 0.0f;
            float4 Ra = make_float4(0.f, 0.f, 0.f, 0.f);
            float4 Rb = make_float4(0.f, 0.f, 0.f, 0.f);

            if (step == 0)
                attn_pass<true >(x, row0[gi] + oct, row1[gi], ol, omask, qa, qb, m, s, Ra, Rb);
            else
                attn_pass<false>(x, row0[gi] + oct, row1[gi], ol, omask, qa, qb, m, s, Ra, Rb);

            // combine 32 octet partials
            if (ol == 0) { s_rm[oct] = m; s_rs[oct] = s; }
            ((float4*)s_rR[oct])[2 * ol]     = Ra;
            ((float4*)s_rR[oct])[2 * ol + 1] = Rb;
            __syncthreads();
            if (t < 64) {
                float M = -FLT_MAX;
                #pragma unroll 8
                for (int p = 0; p < 32; p++) M = fmaxf(M, s_rm[p]);
                float st = 0.0f, Rk = 0.0f;
                #pragma unroll 8
                for (int p = 0; p < 32; p++) {
                    float w = __expf(s_rm[p] - M);
                    st += w * s_rs[p];
                    Rk += w * s_rR[p][t];
                }
                s_act[gi][64 + t] = Rk / fmaxf(st, 1e-16f);   // r
            }
            __syncthreads();
        }
    }

    // ---- final MLP per graph: 128 -> 256 (relu) -> 128 ----
    for (int gi = 0; gi < ngr; gi++) {
        {
            float acc = b1[t];
            const float4* a = (const float4*)s_act[gi];
            #pragma unroll 8
            for (int k4 = 0; k4 < 32; k4++) {
                float4 w = d_W1p[k4 * 256 + t];
                float4 v = a[k4];
                acc += w.x * v.x + w.y * v.y + w.z * v.z + w.w * v.w;
            }
            s_g[0][t] = fmaxf(acc, 0.0f);
        }
        __syncthreads();
        if (t < 128) {
            float acc = b2[t];
            const float4* hv = (const float4*)s_g[0];
            #pragma unroll 8
            for (int k4 = 0; k4 < 64; k4++) {
                float4 w = d_W2p[k4 * 128 + t];
                float4 v = hv[k4];
                acc += w.x * v.x + w.y * v.y + w.z * v.z + w.w * v.w;
            }
            out[(size_t)(g0 + gi) * 128 + t] = acc;
        }
        __syncthreads();
    }
}

extern "C" void kernel_launch(void* const* d_in, const int* in_sizes, int n_in,
                              void* d_out, int out_size) {
    const float* x     = (const float*)d_in[0];
    const int*   batch = (const int*)d_in[1];     // int32 (JAX x64 disabled)
    const float* Wih   = (const float*)d_in[2];
    const float* Whh   = (const float*)d_in[3];
    const float* bih   = (const float*)d_in[4];
    const float* bhh   = (const float*)d_in[5];
    const float* W1    = (const float*)d_in[6];
    const float* b1    = (const float*)d_in[7];
    const float* W2    = (const float*)d_in[8];
    const float* b2    = (const float*)d_in[9];

    int n = in_sizes[0] / HDIM;   // number of nodes

    seg_kernel<<<(n + 511) / 512, 512>>>(batch, n);
    pack_kernel<<<16, 512>>>(Wih, Whh, bih, bhh, W1, W2);
    fused_kernel<<<CTAS, 256>>>(x, b1, b2, (float*)d_out, n);
}

// round 6
// speedup vs baseline: 1.3579x; 1.1218x over previous
#include <cuda_runtime.h>
#include <cuda_fp16.h>
#include <cstdint>
#include <float.h>

#define NGRAPH 1024
#define HDIM   64
#define NMAX   1000000
#define CTAS   296        // 2 x 148 SMs -> exactly one balanced wave at occ 2

// ---------------- device scratch (no allocation allowed) ----------------
__device__ float4 d_WL[32 * 256];    // packed LSTM weights: K=128 (h folded), [k4][n]
__device__ float  d_bsum[256];       // b_ih + b_hh
__device__ float4 d_W1p[32 * 256];   // W1 packed [k4][n]
__device__ float4 d_W2p[64 * 128];   // W2 packed [k4][n]
__device__ int    d_seg[NGRAPH + 1]; // segment row offsets
__device__ uint4  d_xh[NMAX * 8];    // fp16 copy of x (row = 64 halves = 8 uint4)

// ---------------- prep: segment offsets + weight packing in ONE kernel ----------------
__global__ void prep_kernel(const int* __restrict__ batch, int n,
                            const float* __restrict__ Wih, const float* __restrict__ Whh,
                            const float* __restrict__ bih, const float* __restrict__ bhh,
                            const float* __restrict__ W1,  const float* __restrict__ W2) {
    int t = blockIdx.x * blockDim.x + threadIdx.x;
    // segment offsets (sorted int32 batch; reference's int64 is int32 w/ JAX x64 off)
    if (t < n) {
        int b = batch[t];
        b = min(max(b, 0), NGRAPH - 1);
        int bp;
        if (t == 0) bp = -1;
        else {
            bp = batch[t - 1];
            bp = min(max(bp, 0), NGRAPH - 1);
        }
        for (int v = bp + 1; v <= b; v++) d_seg[v] = t;
        if (t == n - 1) {
            for (int v = b + 1; v <= NGRAPH; v++) d_seg[v] = n;
        }
    }
    // weight packing:
    // gates = h @ (W_ih[:, :64] + W_hh).T + r @ W_ih[:, 64:].T + (b_ih + b_hh)
    if (t < 32 * 256) {
        int k4 = t >> 8, nn = t & 255;
        float4 w; float* wp = (float*)&w;
        #pragma unroll
        for (int j = 0; j < 4; j++) {
            int k = k4 * 4 + j;
            if (k < 64) wp[j] = Wih[nn * 128 + k] + Whh[nn * 64 + k];
            else        wp[j] = Wih[nn * 128 + k];
        }
        d_WL[t] = w;
        float4 w1; float* w1p = (float*)&w1;
        #pragma unroll
        for (int j = 0; j < 4; j++) w1p[j] = W1[nn * 128 + k4 * 4 + j];
        d_W1p[t] = w1;
    }
    if (t < 256) d_bsum[t] = bih[t] + bhh[t];
    if (t < 64 * 128) {
        int k4 = t >> 7, nn = t & 127;
        float4 w; float* wp = (float*)&w;
        #pragma unroll
        for (int j = 0; j < 4; j++) wp[j] = W2[nn * 256 + k4 * 4 + j];
        d_W2p[t] = w;
    }
}

__device__ __forceinline__ float sigmoidf_(float v) {
    return 1.0f / (1.0f + __expf(-v));
}

// load 32B slice (16 cols) of row i for lane ql; FIRST: fp32 read + fp16 copy store
template<bool FIRST>
__device__ __forceinline__ float load_dot(const float* __restrict__ x, int i, int ql,
                                          const float4& q0, const float4& q1,
                                          const float4& q2, const float4& q3,
                                          float4& v0, float4& v1, float4& v2, float4& v3) {
    if (FIRST) {
        const float4* rp = (const float4*)(x + (size_t)i * 64) + 4 * ql;
        v0 = __ldcs(rp + 0);
        v1 = __ldcs(rp + 1);
        v2 = __ldcs(rp + 2);
        v3 = __ldcs(rp + 3);
        union { uint4 u; __half2 h[4]; } pk0, pk1;
        pk0.h[0] = __floats2half2_rn(v0.x, v0.y);
        pk0.h[1] = __floats2half2_rn(v0.z, v0.w);
        pk0.h[2] = __floats2half2_rn(v1.x, v1.y);
        pk0.h[3] = __floats2half2_rn(v1.z, v1.w);
        pk1.h[0] = __floats2half2_rn(v2.x, v2.y);
        pk1.h[1] = __floats2half2_rn(v2.z, v2.w);
        pk1.h[2] = __floats2half2_rn(v3.x, v3.y);
        pk1.h[3] = __floats2half2_rn(v3.z, v3.w);
        __stcs(&d_xh[(size_t)i * 8 + 2 * ql],     pk0.u);
        __stcs(&d_xh[(size_t)i * 8 + 2 * ql + 1], pk1.u);
    } else {
        union { uint4 u; __half2 h[4]; } pk0, pk1;
        pk0.u = __ldcs(&d_xh[(size_t)i * 8 + 2 * ql]);
        pk1.u = __ldcs(&d_xh[(size_t)i * 8 + 2 * ql + 1]);
        float2 f;
        f = __half22float2(pk0.h[0]); v0.x = f.x; v0.y = f.y;
        f = __half22float2(pk0.h[1]); v0.z = f.x; v0.w = f.y;
        f = __half22float2(pk0.h[2]); v1.x = f.x; v1.y = f.y;
        f = __half22float2(pk0.h[3]); v1.z = f.x; v1.w = f.y;
        f = __half22float2(pk1.h[0]); v2.x = f.x; v2.y = f.y;
        f = __half22float2(pk1.h[1]); v2.z = f.x; v2.w = f.y;
        f = __half22float2(pk1.h[2]); v3.x = f.x; v3.y = f.y;
        f = __half22float2(pk1.h[3]); v3.z = f.x; v3.w = f.y;
    }
    return v0.x * q0.x + v0.y * q0.y + v0.z * q0.z + v0.w * q0.w
         + v1.x * q1.x + v1.y * q1.y + v1.z * q1.z + v1.w * q1.w
         + v2.x * q2.x + v2.y * q2.y + v2.z * q2.z + v2.w * q2.w
         + v3.x * q3.x + v3.y * q3.y + v3.z * q3.z + v3.w * q3.w;
}

__device__ __forceinline__ void acc4(float& s, float4& R0, float4& R1, float4& R2, float4& R3,
                                     float d, const float4& v0, const float4& v1,
                                     const float4& v2, const float4& v3) {
    s += d;
    R0.x += d * v0.x; R0.y += d * v0.y; R0.z += d * v0.z; R0.w += d * v0.w;
    R1.x += d * v1.x; R1.y += d * v1.y; R1.z += d * v1.z; R1.w += d * v1.w;
    R2.x += d * v2.x; R2.y += d * v2.y; R2.z += d * v2.z; R2.w += d * v2.w;
    R3.x += d * v3.x; R3.y += d * v3.y; R3.z += d * v3.z; R3.w += d * v3.w;
}

__device__ __forceinline__ void rescale4(float& s, float4& R0, float4& R1, float4& R2, float4& R3,
                                         float sc) {
    s *= sc;
    R0.x *= sc; R0.y *= sc; R0.z *= sc; R0.w *= sc;
    R1.x *= sc; R1.y *= sc; R1.z *= sc; R1.w *= sc;
    R2.x *= sc; R2.y *= sc; R2.z *= sc; R2.w *= sc;
    R3.x *= sc; R3.y *= sc; R3.z *= sc; R3.w *= sc;
}

// one attention streaming pass; quad = 4 lanes/row, batch 2 rows, online softmax
template<bool FIRST>
__device__ __forceinline__ void attn_pass(const float* __restrict__ x,
                                          int i, int end, int ql, unsigned qmask,
                                          const float4& q0, const float4& q1,
                                          const float4& q2, const float4& q3,
                                          float& m, float& s,
                                          float4& R0, float4& R1, float4& R2, float4& R3) {
    for (; i + 64 < end; i += 128) {
        float4 u0, u1, u2, u3, w0, w1, w2, w3;
        float pu = load_dot<FIRST>(x, i,      ql, q0, q1, q2, q3, u0, u1, u2, u3);
        float pw = load_dot<FIRST>(x, i + 64, ql, q0, q1, q2, q3, w0, w1, w2, w3);
        pu += __shfl_xor_sync(qmask, pu, 1);
        pw += __shfl_xor_sync(qmask, pw, 1);
        pu += __shfl_xor_sync(qmask, pu, 2);
        pw += __shfl_xor_sync(qmask, pw, 2);
        float P = fmaxf(pu, pw);
        if (P > m) {
            rescale4(s, R0, R1, R2, R3, __expf(m - P));
            m = P;
        }
        acc4(s, R0, R1, R2, R3, __expf(pu - m), u0, u1, u2, u3);
        acc4(s, R0, R1, R2, R3, __expf(pw - m), w0, w1, w2, w3);
    }
    if (i < end) {
        float4 u0, u1, u2, u3;
        float p = load_dot<FIRST>(x, i, ql, q0, q1, q2, q3, u0, u1, u2, u3);
        p += __shfl_xor_sync(qmask, p, 1);
        p += __shfl_xor_sync(qmask, p, 2);
        if (p > m) {
            rescale4(s, R0, R1, R2, R3, __expf(m - p));
            m = p;
        }
        acc4(s, R0, R1, R2, R3, __expf(p - m), u0, u1, u2, u3);
    }
}

// ---------------- fused Set2Set + MLP: 296 CTAs, dynamic graph partition ----------------
__global__ __launch_bounds__(256, 2)
void fused_kernel(const float* __restrict__ x,
                  const float* __restrict__ b1,
                  const float* __restrict__ b2,
                  float* __restrict__ out, int n) {
    __shared__ float s_act[4][128];   // per graph slot: [h(64) | r(64)]
    __shared__ float s_c[4][64];
    __shared__ float s_g[4][256];     // gates; s_g[0] reused as MLP hidden
    __shared__ float s_rm[64], s_rs[64];
    __shared__ float s_rR[64][64];

    const int t  = threadIdx.x;
    const int c  = blockIdx.x;
    const int qd = t >> 2;            // quad id 0..63
    const int ql = t & 3;             // lane within quad
    const unsigned qmask = 0xFu << (t & 28);

    const int g0  = (c * NGRAPH) / CTAS;
    const int g1  = ((c + 1) * NGRAPH) / CTAS;
    const int ngr = g1 - g0;          // 3 or 4

    if (t < 128) {
        #pragma unroll
        for (int gi = 0; gi < 4; gi++) {
            s_act[gi][t] = 0.0f;
            if (t < 64) s_c[gi][t] = 0.0f;
        }
    }
    int row0[4], row1[4];
    #pragma unroll
    for (int gi = 0; gi < 4; gi++) {
        int gg = min(g0 + gi, NGRAPH - 1);
        int a = d_seg[gg];
        int b = d_seg[gg + 1];
        a = min(max(a, 0), n);
        b = min(max(b, a), n);
        row0[gi] = a;
        row1[gi] = b;
    }
    __syncthreads();

    for (int step = 0; step < 5; step++) {
        // ---- LSTM gates: 256 threads = 256 gates, all graph slots per thread ----
        {
            float acc0 = d_bsum[t], acc1 = acc0, acc2 = acc0, acc3 = acc0;
            const float4* a0 = (const float4*)s_act[0];
            const float4* a1 = (const float4*)s_act[1];
            const float4* a2 = (const float4*)s_act[2];
            const float4* a3 = (const float4*)s_act[3];
            #pragma unroll 8
            for (int k4 = 0; k4 < 32; k4++) {
                float4 w  = d_WL[k4 * 256 + t];
                float4 v0 = a0[k4];
                float4 v1 = a1[k4];
                float4 v2 = a2[k4];
                float4 v3 = a3[k4];
                acc0 += w.x * v0.x + w.y * v0.y + w.z * v0.z + w.w * v0.w;
                acc1 += w.x * v1.x + w.y * v1.y + w.z * v1.z + w.w * v1.w;
                acc2 += w.x * v2.x + w.y * v2.y + w.z * v2.z + w.w * v2.w;
                acc3 += w.x * v3.x + w.y * v3.y + w.z * v3.z + w.w * v3.w;
            }
            s_g[0][t] = acc0;
            s_g[1][t] = acc1;
            s_g[2][t] = acc2;
            s_g[3][t] = acc3;
        }
        __syncthreads();
        {
            const int gi = t >> 6, k = t & 63;   // 4 graphs x 64 lanes = 256 threads
            float gc = sigmoidf_(s_g[gi][k]);
            float gf = sigmoidf_(s_g[gi][64 + k]);
            float gg = tanhf(s_g[gi][128 + k]);
            float go = sigmoidf_(s_g[gi][192 + k]);
            float cc = gf * s_c[gi][k] + gc * gg;
            s_c[gi][k] = cc;
            s_act[gi][k] = go * tanhf(cc);       // h (== q)
        }
        __syncthreads();

        // ---- attention per graph: single streaming pass, online softmax ----
        for (int gi = 0; gi < ngr; gi++) {
            const float4 q0 = ((const float4*)s_act[gi])[4 * ql];
            const float4 q1 = ((const float4*)s_act[gi])[4 * ql + 1];
            const float4 q2 = ((const float4*)s_act[gi])[4 * ql + 2];
            const float4 q3 = ((const float4*)s_act[gi])[4 * ql + 3];
            float m = -FLT_MAX, s = 0.0f;
            float4 R0 = make_float4(0.f, 0.f, 0.f, 0.f);
            float4 R1 = R0, R2 = R0, R3 = R0;

            if (step == 0)
                attn_pass<true >(x, row0[gi] + qd, row1[gi], ql, qmask,
                                 q0, q1, q2, q3, m, s, R0, R1, R2, R3);
            else
                attn_pass<false>(x, row0[gi] + qd, row1[gi], ql, qmask,
                                 q0, q1, q2, q3, m, s, R0, R1, R2, R3);

            // combine 64 quad partials
            if (ql == 0) { s_rm[qd] = m; s_rs[qd] = s; }
            ((float4*)s_rR[qd])[4 * ql]     = R0;
            ((float4*)s_rR[qd])[4 * ql + 1] = R1;
            ((float4*)s_rR[qd])[4 * ql + 2] = R2;
            ((float4*)s_rR[qd])[4 * ql + 3] = R3;
            __syncthreads();
            if (t < 64) {
                float M = -FLT_MAX;
                #pragma unroll 16
                for (int p = 0; p < 64; p++) M = fmaxf(M, s_rm[p]);
                float st = 0.0f, Rk = 0.0f;
                #pragma unroll 16
                for (int p = 0; p < 64; p++) {
                    float w = __expf(s_rm[p] - M);
                    st += w * s_rs[p];
                    Rk += w * s_rR[p][t];
                }
                s_act[gi][64 + t] = Rk / fmaxf(st, 1e-16f);   // r
            }
            __syncthreads();
        }
    }

    // ---- final MLP per graph: 128 -> 256 (relu) -> 128 ----
    for (int gi = 0; gi < ngr; gi++) {
        {
            float acc = b1[t];
            const float4* a = (const float4*)s_act[gi];
            #pragma unroll 8
            for (int k4 = 0; k4 < 32; k4++) {
                float4 w = d_W1p[k4 * 256 + t];
                float4 v = a[k4];
                acc += w.x * v.x + w.y * v.y + w.z * v.z + w.w * v.w;
            }
            s_g[0][t] = fmaxf(acc, 0.0f);
        }
        __syncthreads();
        if (t < 128) {
            float acc = b2[t];
            const float4* hv = (const float4*)s_g[0];
            #pragma unroll 8
            for (int k4 = 0; k4 < 64; k4++) {
                float4 w = d_W2p[k4 * 128 + t];
                float4 v = hv[k4];
                acc += w.x * v.x + w.y * v.y + w.z * v.z + w.w * v.w;
            }
            out[(size_t)(g0 + gi) * 128 + t] = acc;
        }
        __syncthreads();
    }
}

extern "C" void kernel_launch(void* const* d_in, const int* in_sizes, int n_in,
                              void* d_out, int out_size) {
    const float* x     = (const float*)d_in[0];
    const int*   batch = (const int*)d_in[1];     // int32 (JAX x64 disabled)
    const float* Wih   = (const float*)d_in[2];
    const float* Whh   = (const float*)d_in[3];
    const float* bih   = (const float*)d_in[4];
    const float* bhh   = (const float*)d_in[5];
    const float* W1    = (const float*)d_in[6];
    const float* b1    = (const float*)d_in[7];
    const float* W2    = (const float*)d_in[8];
    const float* b2    = (const float*)d_in[9];

    int n = in_sizes[0] / HDIM;   // number of nodes

    prep_kernel<<<(n + 511) / 512, 512>>>(batch, n, Wih, Whh, bih, bhh, W1, W2);
    fused_kernel<<<CTAS, 256>>>(x, b1, b2, (float*)d_out, n);
}

// round 7
// speedup vs baseline: 1.4232x; 1.0481x over previous
#include <cuda_runtime.h>
#include <cuda_fp16.h>
#include <cstdint>
#include <float.h>

#define NGRAPH 1024
#define HDIM   64
#define NMAX   1000000
#define CTAS   296        // 2 x 148 SMs -> exactly one balanced wave at occ 2

// ---------------- device scratch (no allocation allowed) ----------------
__device__ float4 d_WL[32 * 256];    // packed LSTM weights: K=128 (h folded), [k4][n]
__device__ float  d_bsum[256];       // b_ih + b_hh
__device__ float4 d_W1p[32 * 256];   // W1 packed [k4][n]
__device__ float4 d_W2p[64 * 128];   // W2 packed [k4][n]
__device__ int    d_seg[NGRAPH + 1]; // segment row offsets
__device__ uint4  d_xh[NMAX * 8];    // fp16 copy of x (row = 64 halves = 8 uint4)

// ---------------- prep: segment offsets + weight packing in ONE kernel ----------------
__global__ void prep_kernel(const int* __restrict__ batch, int n,
                            const float* __restrict__ Wih, const float* __restrict__ Whh,
                            const float* __restrict__ bih, const float* __restrict__ bhh,
                            const float* __restrict__ W1,  const float* __restrict__ W2) {
    int t = blockIdx.x * blockDim.x + threadIdx.x;
    // segment offsets (sorted int32 batch; reference's int64 is int32 w/ JAX x64 off)
    if (t < n) {
        int b = batch[t];
        b = min(max(b, 0), NGRAPH - 1);
        int bp;
        if (t == 0) bp = -1;
        else {
            bp = batch[t - 1];
            bp = min(max(bp, 0), NGRAPH - 1);
        }
        for (int v = bp + 1; v <= b; v++) d_seg[v] = t;
        if (t == n - 1) {
            for (int v = b + 1; v <= NGRAPH; v++) d_seg[v] = n;
        }
    }
    // weight packing:
    // gates = h @ (W_ih[:, :64] + W_hh).T + r @ W_ih[:, 64:].T + (b_ih + b_hh)
    if (t < 32 * 256) {
        int k4 = t >> 8, nn = t & 255;
        float4 w; float* wp = (float*)&w;
        #pragma unroll
        for (int j = 0; j < 4; j++) {
            int k = k4 * 4 + j;
            if (k < 64) wp[j] = Wih[nn * 128 + k] + Whh[nn * 64 + k];
            else        wp[j] = Wih[nn * 128 + k];
        }
        d_WL[t] = w;
        float4 w1; float* w1p = (float*)&w1;
        #pragma unroll
        for (int j = 0; j < 4; j++) w1p[j] = W1[nn * 128 + k4 * 4 + j];
        d_W1p[t] = w1;
    }
    if (t < 256) d_bsum[t] = bih[t] + bhh[t];
    if (t < 64 * 128) {
        int k4 = t >> 7, nn = t & 127;
        float4 w; float* wp = (float*)&w;
        #pragma unroll
        for (int j = 0; j < 4; j++) wp[j] = W2[nn * 256 + k4 * 4 + j];
        d_W2p[t] = w;
    }
}

__device__ __forceinline__ float sigmoidf_(float v) {
    return 1.0f / (1.0f + __expf(-v));
}

// load 32B slice (16 cols) of row i for lane ql; FIRST: fp32 read + fp16 copy store
template<bool FIRST>
__device__ __forceinline__ float load_dot(const float* __restrict__ x, int i, int ql,
                                          const float4& q0, const float4& q1,
                                          const float4& q2, const float4& q3,
                                          float4& v0, float4& v1, float4& v2, float4& v3) {
    if (FIRST) {
        const float4* rp = (const float4*)(x + (size_t)i * 64) + 4 * ql;
        v0 = __ldcs(rp + 0);
        v1 = __ldcs(rp + 1);
        v2 = __ldcs(rp + 2);
        v3 = __ldcs(rp + 3);
        union { uint4 u; __half2 h[4]; } pk0, pk1;
        pk0.h[0] = __floats2half2_rn(v0.x, v0.y);
        pk0.h[1] = __floats2half2_rn(v0.z, v0.w);
        pk0.h[2] = __floats2half2_rn(v1.x, v1.y);
        pk0.h[3] = __floats2half2_rn(v1.z, v1.w);
        pk1.h[0] = __floats2half2_rn(v2.x, v2.y);
        pk1.h[1] = __floats2half2_rn(v2.z, v2.w);
        pk1.h[2] = __floats2half2_rn(v3.x, v3.y);
        pk1.h[3] = __floats2half2_rn(v3.z, v3.w);
        __stcs(&d_xh[(size_t)i * 8 + 2 * ql],     pk0.u);
        __stcs(&d_xh[(size_t)i * 8 + 2 * ql + 1], pk1.u);
    } else {
        union { uint4 u; __half2 h[4]; } pk0, pk1;
        pk0.u = __ldcs(&d_xh[(size_t)i * 8 + 2 * ql]);
        pk1.u = __ldcs(&d_xh[(size_t)i * 8 + 2 * ql + 1]);
        float2 f;
        f = __half22float2(pk0.h[0]); v0.x = f.x; v0.y = f.y;
        f = __half22float2(pk0.h[1]); v0.z = f.x; v0.w = f.y;
        f = __half22float2(pk0.h[2]); v1.x = f.x; v1.y = f.y;
        f = __half22float2(pk0.h[3]); v1.z = f.x; v1.w = f.y;
        f = __half22float2(pk1.h[0]); v2.x = f.x; v2.y = f.y;
        f = __half22float2(pk1.h[1]); v2.z = f.x; v2.w = f.y;
        f = __half22float2(pk1.h[2]); v3.x = f.x; v3.y = f.y;
        f = __half22float2(pk1.h[3]); v3.z = f.x; v3.w = f.y;
    }
    return v0.x * q0.x + v0.y * q0.y + v0.z * q0.z + v0.w * q0.w
         + v1.x * q1.x + v1.y * q1.y + v1.z * q1.z + v1.w * q1.w
         + v2.x * q2.x + v2.y * q2.y + v2.z * q2.z + v2.w * q2.w
         + v3.x * q3.x + v3.y * q3.y + v3.z * q3.z + v3.w * q3.w;
}

__device__ __forceinline__ void acc4(float& s, float4& R0, float4& R1, float4& R2, float4& R3,
                                     float d, const float4& v0, const float4& v1,
                                     const float4& v2, const float4& v3) {
    s += d;
    R0.x += d * v0.x; R0.y += d * v0.y; R0.z += d * v0.z; R0.w += d * v0.w;
    R1.x += d * v1.x; R1.y += d * v1.y; R1.z += d * v1.z; R1.w += d * v1.w;
    R2.x += d * v2.x; R2.y += d * v2.y; R2.z += d * v2.z; R2.w += d * v2.w;
    R3.x += d * v3.x; R3.y += d * v3.y; R3.z += d * v3.z; R3.w += d * v3.w;
}

__device__ __forceinline__ void rescale4(float& s, float4& R0, float4& R1, float4& R2, float4& R3,
                                         float sc) {
    s *= sc;
    R0.x *= sc; R0.y *= sc; R0.z *= sc; R0.w *= sc;
    R1.x *= sc; R1.y *= sc; R1.z *= sc; R1.w *= sc;
    R2.x *= sc; R2.y *= sc; R2.z *= sc; R2.w *= sc;
    R3.x *= sc; R3.y *= sc; R3.z *= sc; R3.w *= sc;
}

// one attention streaming pass; quad = 4 lanes/row, batch 4 rows (MLP 4), online softmax
template<bool FIRST>
__device__ __forceinline__ void attn_pass(const float* __restrict__ x,
                                          int i, int end, int ql, unsigned qmask,
                                          const float4& q0, const float4& q1,
                                          const float4& q2, const float4& q3,
                                          float& m, float& s,
                                          float4& R0, float4& R1, float4& R2, float4& R3) {
    for (; i + 192 < end; i += 256) {
        float4 a0, a1, a2, a3, b0, b1, b2, b3;
        float4 c0, c1, c2, c3, e0, e1, e2, e3;
        float pa = load_dot<FIRST>(x, i,       ql, q0, q1, q2, q3, a0, a1, a2, a3);
        float pb = load_dot<FIRST>(x, i + 64,  ql, q0, q1, q2, q3, b0, b1, b2, b3);
        float pc = load_dot<FIRST>(x, i + 128, ql, q0, q1, q2, q3, c0, c1, c2, c3);
        float pe = load_dot<FIRST>(x, i + 192, ql, q0, q1, q2, q3, e0, e1, e2, e3);
        pa += __shfl_xor_sync(qmask, pa, 1);
        pb += __shfl_xor_sync(qmask, pb, 1);
        pc += __shfl_xor_sync(qmask, pc, 1);
        pe += __shfl_xor_sync(qmask, pe, 1);
        pa += __shfl_xor_sync(qmask, pa, 2);
        pb += __shfl_xor_sync(qmask, pb, 2);
        pc += __shfl_xor_sync(qmask, pc, 2);
        pe += __shfl_xor_sync(qmask, pe, 2);
        float P = fmaxf(fmaxf(pa, pb), fmaxf(pc, pe));
        if (P > m) {
            rescale4(s, R0, R1, R2, R3, __expf(m - P));
            m = P;
        }
        acc4(s, R0, R1, R2, R3, __expf(pa - m), a0, a1, a2, a3);
        acc4(s, R0, R1, R2, R3, __expf(pb - m), b0, b1, b2, b3);
        acc4(s, R0, R1, R2, R3, __expf(pc - m), c0, c1, c2, c3);
        acc4(s, R0, R1, R2, R3, __expf(pe - m), e0, e1, e2, e3);
    }
    for (; i < end; i += 64) {
        float4 a0, a1, a2, a3;
        float p = load_dot<FIRST>(x, i, ql, q0, q1, q2, q3, a0, a1, a2, a3);
        p += __shfl_xor_sync(qmask, p, 1);
        p += __shfl_xor_sync(qmask, p, 2);
        if (p > m) {
            rescale4(s, R0, R1, R2, R3, __expf(m - p));
            m = p;
        }
        acc4(s, R0, R1, R2, R3, __expf(p - m), a0, a1, a2, a3);
    }
}

// ---------------- fused Set2Set + MLP: 296 CTAs, dynamic graph partition ----------------
__global__ __launch_bounds__(256, 2)
void fused_kernel(const float* __restrict__ x,
                  const float* __restrict__ b1,
                  const float* __restrict__ b2,
                  float* __restrict__ out, int n) {
    __shared__ float s_act[4][128];   // per graph slot: [h(64) | r(64)]
    __shared__ float s_c[4][64];
    __shared__ float s_g[4][256];     // gates; s_g[0] reused as MLP hidden
    __shared__ float s_rm[64], s_rs[64];
    __shared__ float s_rR[64][64];

    const int t  = threadIdx.x;
    const int c  = blockIdx.x;
    const int qd = t >> 2;            // quad id 0..63
    const int ql = t & 3;             // lane within quad
    const unsigned qmask = 0xFu << (t & 28);

    const int g0  = (c * NGRAPH) / CTAS;
    const int g1  = ((c + 1) * NGRAPH) / CTAS;
    const int ngr = g1 - g0;          // 3 or 4

    if (t < 128) {
        #pragma unroll
        for (int gi = 0; gi < 4; gi++) {
            s_act[gi][t] = 0.0f;
            if (t < 64) s_c[gi][t] = 0.0f;
        }
    }
    int row0[4], row1[4];
    #pragma unroll
    for (int gi = 0; gi < 4; gi++) {
        int gg = min(g0 + gi, NGRAPH - 1);
        int a = d_seg[gg];
        int b = d_seg[gg + 1];
        a = min(max(a, 0), n);
        b = min(max(b, a), n);
        row0[gi] = a;
        row1[gi] = b;
    }
    __syncthreads();

    for (int step = 0; step < 5; step++) {
        // ---- LSTM gates: 256 threads = 256 gates, all graph slots per thread ----
        {
            float acc0 = d_bsum[t], acc1 = acc0, acc2 = acc0, acc3 = acc0;
            const float4* a0 = (const float4*)s_act[0];
            const float4* a1 = (const float4*)s_act[1];
            const float4* a2 = (const float4*)s_act[2];
            const float4* a3 = (const float4*)s_act[3];
            #pragma unroll 8
            for (int k4 = 0; k4 < 32; k4++) {
                float4 w  = d_WL[k4 * 256 + t];
                float4 v0 = a0[k4];
                float4 v1 = a1[k4];
                float4 v2 = a2[k4];
                float4 v3 = a3[k4];
                acc0 += w.x * v0.x + w.y * v0.y + w.z * v0.z + w.w * v0.w;
                acc1 += w.x * v1.x + w.y * v1.y + w.z * v1.z + w.w * v1.w;
                acc2 += w.x * v2.x + w.y * v2.y + w.z * v2.z + w.w * v2.w;
                acc3 += w.x * v3.x + w.y * v3.y + w.z * v3.z + w.w * v3.w;
            }
            s_g[0][t] = acc0;
            s_g[1][t] = acc1;
            s_g[2][t] = acc2;
            s_g[3][t] = acc3;
        }
        __syncthreads();
        {
            const int gi = t >> 6, k = t & 63;   // 4 graphs x 64 lanes = 256 threads
            float gc = sigmoidf_(s_g[gi][k]);
            float gf = sigmoidf_(s_g[gi][64 + k]);
            float gg = tanhf(s_g[gi][128 + k]);
            float go = sigmoidf_(s_g[gi][192 + k]);
            float cc = gf * s_c[gi][k] + gc * gg;
            s_c[gi][k] = cc;
            s_act[gi][k] = go * tanhf(cc);       // h (== q)
        }
        __syncthreads();

        // ---- attention per graph: single streaming pass, online softmax ----
        for (int gi = 0; gi < ngr; gi++) {
            const float4 q0 = ((const float4*)s_act[gi])[4 * ql];
            const float4 q1 = ((const float4*)s_act[gi])[4 * ql + 1];
            const float4 q2 = ((const float4*)s_act[gi])[4 * ql + 2];
            const float4 q3 = ((const float4*)s_act[gi])[4 * ql + 3];
            float m = -FLT_MAX, s = 0.0f;
            float4 R0 = make_float4(0.f, 0.f, 0.f, 0.f);
            float4 R1 = R0, R2 = R0, R3 = R0;

            if (step == 0)
                attn_pass<true >(x, row0[gi] + qd, row1[gi], ql, qmask,
                                 q0, q1, q2, q3, m, s, R0, R1, R2, R3);
            else
                attn_pass<false>(x, row0[gi] + qd, row1[gi], ql, qmask,
                                 q0, q1, q2, q3, m, s, R0, R1, R2, R3);

            // combine 64 quad partials
            if (ql == 0) { s_rm[qd] = m; s_rs[qd] = s; }
            ((float4*)s_rR[qd])[4 * ql]     = R0;
            ((float4*)s_rR[qd])[4 * ql + 1] = R1;
            ((float4*)s_rR[qd])[4 * ql + 2] = R2;
            ((float4*)s_rR[qd])[4 * ql + 3] = R3;
            __syncthreads();
            if (t < 64) {
                float M = -FLT_MAX;
                #pragma unroll 16
                for (int p = 0; p < 64; p++) M = fmaxf(M, s_rm[p]);
                float st = 0.0f, Rk = 0.0f;
                #pragma unroll 16
                for (int p = 0; p < 64; p++) {
                    float w = __expf(s_rm[p] - M);
                    st += w * s_rs[p];
                    Rk += w * s_rR[p][t];
                }
                s_act[gi][64 + t] = Rk / fmaxf(st, 1e-16f);   // r
            }
            __syncthreads();
        }
    }

    // ---- final MLP per graph: 128 -> 256 (relu) -> 128 ----
    for (int gi = 0; gi < ngr; gi++) {
        {
            float acc = b1[t];
            const float4* a = (const float4*)s_act[gi];
            #pragma unroll 8
            for (int k4 = 0; k4 < 32; k4++) {
                float4 w = d_W1p[k4 * 256 + t];
                float4 v = a[k4];
                acc += w.x * v.x + w.y * v.y + w.z * v.z + w.w * v.w;
            }
            s_g[0][t] = fmaxf(acc, 0.0f);
        }
        __syncthreads();
        if (t < 128) {
            float acc = b2[t];
            const float4* hv = (const float4*)s_g[0];
            #pragma unroll 8
            for (int k4 = 0; k4 < 64; k4++) {
                float4 w = d_W2p[k4 * 128 + t];
                float4 v = hv[k4];
                acc += w.x * v.x + w.y * v.y + w.z * v.z + w.w * v.w;
            }
            out[(size_t)(g0 + gi) * 128 + t] = acc;
        }
        __syncthreads();
    }
}

extern "C" void kernel_launch(void* const* d_in, const int* in_sizes, int n_in,
                              void* d_out, int out_size) {
    const float* x     = (const float*)d_in[0];
    const int*   batch = (const int*)d_in[1];     // int32 (JAX x64 disabled)
    const float* Wih   = (const float*)d_in[2];
    const float* Whh   = (const float*)d_in[3];
    const float* bih   = (const float*)d_in[4];
    const float* bhh   = (const float*)d_in[5];
    const float* W1    = (const float*)d_in[6];
    const float* b1    = (const float*)d_in[7];
    const float* W2    = (const float*)d_in[8];
    const float* b2    = (const float*)d_in[9];

    int n = in_sizes[0] / HDIM;   // number of nodes

    prep_kernel<<<(n + 511) / 512, 512>>>(batch, n, Wih, Whh, bih, bhh, W1, W2);
    fused_kernel<<<CTAS, 256>>>(x, b1, b2, (float*)d_out, n);
}

// round 8
// speedup vs baseline: 1.4263x; 1.0022x over previous
#include <cuda_runtime.h>
#include <cuda_fp16.h>
#include <cuda_pipeline.h>
#include <cstdint>
#include <float.h>

#define NGRAPH 1024
#define HDIM   64
#define NMAX   1000000
#define CTAS   296        // 2 x 148 SMs -> one balanced wave at occ 2

// ---------------- device scratch (no allocation allowed) ----------------
__device__ float4 d_WL[32 * 256];    // packed LSTM weights: K=128 (h folded), [k4][n]
__device__ float  d_bsum[256];       // b_ih + b_hh
__device__ float4 d_W1p[32 * 256];   // W1 packed [k4][n]
__device__ float4 d_W2p[64 * 128];   // W2 packed [k4][n]
__device__ int    d_seg[NGRAPH + 1]; // segment row offsets
__device__ uint4  d_xh[NMAX * 8];    // fp16 copy of x (row = 64 halves = 8 uint4)

// dynamic shared memory layout
struct Smem {
    char  stage[8][6144];   // per-warp staging ring: fp32 3x2048B, fp16 4x1024B
    float s_act[4][128];    // per graph slot: [h(64) | r(64)]
    float s_c[4][64];
    float s_g[4][256];      // gates; s_g[0] reused as MLP hidden
    float s_rm[64];
    float s_rs[64];
    float s_rR[64][64];
};

// ---------------- prep: segment offsets + weight packing ----------------
__global__ void prep_kernel(const int* __restrict__ batch, int n,
                            const float* __restrict__ Wih, const float* __restrict__ Whh,
                            const float* __restrict__ bih, const float* __restrict__ bhh,
                            const float* __restrict__ W1,  const float* __restrict__ W2) {
    int t = blockIdx.x * blockDim.x + threadIdx.x;
    if (t < n) {
        int b = batch[t];
        b = min(max(b, 0), NGRAPH - 1);
        int bp;
        if (t == 0) bp = -1;
        else {
            bp = batch[t - 1];
            bp = min(max(bp, 0), NGRAPH - 1);
        }
        for (int v = bp + 1; v <= b; v++) d_seg[v] = t;
        if (t == n - 1) {
            for (int v = b + 1; v <= NGRAPH; v++) d_seg[v] = n;
        }
    }
    // gates = h @ (W_ih[:, :64] + W_hh).T + r @ W_ih[:, 64:].T + (b_ih + b_hh)
    if (t < 32 * 256) {
        int k4 = t >> 8, nn = t & 255;
        float4 w; float* wp = (float*)&w;
        #pragma unroll
        for (int j = 0; j < 4; j++) {
            int k = k4 * 4 + j;
            if (k < 64) wp[j] = Wih[nn * 128 + k] + Whh[nn * 64 + k];
            else        wp[j] = Wih[nn * 128 + k];
        }
        d_WL[t] = w;
        float4 w1; float* w1p = (float*)&w1;
        #pragma unroll
        for (int j = 0; j < 4; j++) w1p[j] = W1[nn * 128 + k4 * 4 + j];
        d_W1p[t] = w1;
    }
    if (t < 256) d_bsum[t] = bih[t] + bhh[t];
    if (t < 64 * 128) {
        int k4 = t >> 7, nn = t & 127;
        float4 w; float* wp = (float*)&w;
        #pragma unroll
        for (int j = 0; j < 4; j++) wp[j] = W2[nn * 256 + k4 * 4 + j];
        d_W2p[t] = w;
    }
}

__device__ __forceinline__ float sigmoidf_(float v) {
    return 1.0f / (1.0f + __expf(-v));
}

// fill one 8-row slice (64-row stride chunk j belongs to this warp's rows)
template<bool FIRST>
__device__ __forceinline__ void fill_slice(char* slot, const float* __restrict__ x,
                                           int srow0, int r1, int lane) {
    int row = srow0 + (lane >> 2);
    row = min(row, r1 - 1);              // clamp: stale-but-finite data for tail rows
    if (FIRST) {
        const char* g = (const char*)(x + (size_t)row * HDIM) + (lane & 3) * 64;
        char* sdst = slot + (lane >> 2) * 256 + (lane & 3) * 64;
        #pragma unroll
        for (int u = 0; u < 4; u++)
            __pipeline_memcpy_async(sdst + u * 16, g + u * 16, 16);
    } else {
        const char* g = (const char*)(&d_xh[(size_t)row * 8]) + (lane & 3) * 32;
        char* sdst = slot + (lane >> 2) * 128 + (lane & 3) * 32;
        #pragma unroll
        for (int u = 0; u < 2; u++)
            __pipeline_memcpy_async(sdst + u * 16, g + u * 16, 16);
    }
}

// consume one row (quad q within warp, lane ql within quad) from a staged slice
template<bool FIRST>
__device__ __forceinline__ void consume_row(const char* slot, int row, int r1,
        int q, int ql,
        const float4& q0, const float4& q1, const float4& q2, const float4& q3,
        float& m, float& s, float4& R0, float4& R1, float4& R2, float4& R3) {
    float4 v0, v1, v2, v3;
    const bool act = (row < r1);
    if (FIRST) {
        const float4* p4 = (const float4*)(slot + q * 256 + ql * 64);
        v0 = p4[0]; v1 = p4[1]; v2 = p4[2]; v3 = p4[3];
        if (act) {  // write fp16 copy for steps 1-4
            union { uint4 u; __half2 h[4]; } pk0, pk1;
            pk0.h[0] = __floats2half2_rn(v0.x, v0.y);
            pk0.h[1] = __floats2half2_rn(v0.z, v0.w);
            pk0.h[2] = __floats2half2_rn(v1.x, v1.y);
            pk0.h[3] = __floats2half2_rn(v1.z, v1.w);
            pk1.h[0] = __floats2half2_rn(v2.x, v2.y);
            pk1.h[1] = __floats2half2_rn(v2.z, v2.w);
            pk1.h[2] = __floats2half2_rn(v3.x, v3.y);
            pk1.h[3] = __floats2half2_rn(v3.z, v3.w);
            __stcs(&d_xh[(size_t)row * 8 + 2 * ql],     pk0.u);
            __stcs(&d_xh[(size_t)row * 8 + 2 * ql + 1], pk1.u);
        }
    } else {
        const uint4* p4 = (const uint4*)(slot + q * 128 + ql * 32);
        union { uint4 u; __half2 h[4]; } pk0, pk1;
        pk0.u = p4[0];
        pk1.u = p4[1];
        float2 f;
        f = __half22float2(pk0.h[0]); v0.x = f.x; v0.y = f.y;
        f = __half22float2(pk0.h[1]); v0.z = f.x; v0.w = f.y;
        f = __half22float2(pk0.h[2]); v1.x = f.x; v1.y = f.y;
        f = __half22float2(pk0.h[3]); v1.z = f.x; v1.w = f.y;
        f = __half22float2(pk1.h[0]); v2.x = f.x; v2.y = f.y;
        f = __half22float2(pk1.h[1]); v2.z = f.x; v2.w = f.y;
        f = __half22float2(pk1.h[2]); v3.x = f.x; v3.y = f.y;
        f = __half22float2(pk1.h[3]); v3.z = f.x; v3.w = f.y;
    }
    float p = v0.x * q0.x + v0.y * q0.y + v0.z * q0.z + v0.w * q0.w
            + v1.x * q1.x + v1.y * q1.y + v1.z * q1.z + v1.w * q1.w
            + v2.x * q2.x + v2.y * q2.y + v2.z * q2.z + v2.w * q2.w
            + v3.x * q3.x + v3.y * q3.y + v3.z * q3.z + v3.w * q3.w;
    p += __shfl_xor_sync(0xffffffffu, p, 1);
    p += __shfl_xor_sync(0xffffffffu, p, 2);
    if (act) {
        if (p > m) {
            float sc = __expf(m - p);
            s *= sc;
            R0.x *= sc; R0.y *= sc; R0.z *= sc; R0.w *= sc;
            R1.x *= sc; R1.y *= sc; R1.z *= sc; R1.w *= sc;
            R2.x *= sc; R2.y *= sc; R2.z *= sc; R2.w *= sc;
            R3.x *= sc; R3.y *= sc; R3.z *= sc; R3.w *= sc;
            m = p;
        }
        float d = __expf(p - m);
        s += d;
        R0.x += d * v0.x; R0.y += d * v0.y; R0.z += d * v0.z; R0.w += d * v0.w;
        R1.x += d * v1.x; R1.y += d * v1.y; R1.z += d * v1.z; R1.w += d * v1.w;
        R2.x += d * v2.x; R2.y += d * v2.y; R2.z += d * v2.z; R2.w += d * v2.w;
        R3.x += d * v3.x; R3.y += d * v3.y; R3.z += d * v3.z; R3.w += d * v3.w;
    }
}

// per-warp streaming attention pass with cp.async ring (no block syncs inside)
template<bool FIRST>
__device__ __forceinline__ void attn_pass(const float* __restrict__ x, char* wstage,
        int r0, int r1, int w, int lane, int q, int ql,
        const float4& q0, const float4& q1, const float4& q2, const float4& q3,
        float& m, float& s, float4& R0, float4& R1, float4& R2, float4& R3) {
    constexpr int S     = FIRST ? 3 : 4;
    constexpr int SLICE = FIRST ? 2048 : 1024;
    const int wrow0 = r0 + w * 8;
    const int iters = (r1 > wrow0) ? ((r1 - wrow0 + 63) >> 6) : 0;
    #pragma unroll
    for (int j = 0; j < S - 1; j++) {
        if (j < iters) fill_slice<FIRST>(wstage + j * SLICE, x, wrow0 + j * 64, r1, lane);
        __pipeline_commit();
    }
    int slot = 0;
    for (int j = 0; j < iters; j++) {
        __pipeline_wait_prior(S - 2);
        consume_row<FIRST>(wstage + slot * SLICE, wrow0 + j * 64 + q, r1, q, ql,
                           q0, q1, q2, q3, m, s, R0, R1, R2, R3);
        __syncwarp();            // all lanes done reading slot before it is refilled
        int jn = j + S - 1;
        int sn = slot + S - 1; if (sn >= S) sn -= S;
        if (jn < iters) fill_slice<FIRST>(wstage + sn * SLICE, x, wrow0 + jn * 64, r1, lane);
        __pipeline_commit();
        slot++; if (slot == S) slot = 0;
    }
}

// ---------------- fused Set2Set + MLP: 296 CTAs, dynamic graph partition ----------------
__global__ __launch_bounds__(256, 2)
void fused_kernel(const float* __restrict__ x,
                  const float* __restrict__ b1,
                  const float* __restrict__ b2,
                  float* __restrict__ out, int n) {
    extern __shared__ char smraw[];
    Smem& S = *(Smem*)smraw;

    const int t    = threadIdx.x;
    const int c    = blockIdx.x;
    const int w    = t >> 5;          // warp 0..7
    const int lane = t & 31;
    const int q    = lane >> 2;       // quad within warp 0..7
    const int ql   = t & 3;           // lane within quad
    const int qd   = t >> 2;          // global quad 0..63
    char* wstage   = S.stage[w];

    const int g0  = (c * NGRAPH) / CTAS;
    const int g1  = ((c + 1) * NGRAPH) / CTAS;
    const int ngr = g1 - g0;          // 3 or 4

    if (t < 128) {
        #pragma unroll
        for (int gi = 0; gi < 4; gi++) {
            S.s_act[gi][t] = 0.0f;
            if (t < 64) S.s_c[gi][t] = 0.0f;
        }
    }
    int row0[4], row1[4];
    #pragma unroll
    for (int gi = 0; gi < 4; gi++) {
        int gg = min(g0 + gi, NGRAPH - 1);
        int a = d_seg[gg];
        int b = d_seg[gg + 1];
        a = min(max(a, 0), n);
        b = min(max(b, a), n);
        row0[gi] = a;
        row1[gi] = b;
    }
    __syncthreads();

    for (int step = 0; step < 5; step++) {
        // ---- LSTM gates: 256 threads = 256 gates, all graph slots per thread ----
        {
            float acc0 = d_bsum[t], acc1 = acc0, acc2 = acc0, acc3 = acc0;
            const float4* a0 = (const float4*)S.s_act[0];
            const float4* a1 = (const float4*)S.s_act[1];
            const float4* a2 = (const float4*)S.s_act[2];
            const float4* a3 = (const float4*)S.s_act[3];
            #pragma unroll 8
            for (int k4 = 0; k4 < 32; k4++) {
                float4 wv = d_WL[k4 * 256 + t];
                float4 v0 = a0[k4];
                float4 v1 = a1[k4];
                float4 v2 = a2[k4];
                float4 v3 = a3[k4];
                acc0 += wv.x * v0.x + wv.y * v0.y + wv.z * v0.z + wv.w * v0.w;
                acc1 += wv.x * v1.x + wv.y * v1.y + wv.z * v1.z + wv.w * v1.w;
                acc2 += wv.x * v2.x + wv.y * v2.y + wv.z * v2.z + wv.w * v2.w;
                acc3 += wv.x * v3.x + wv.y * v3.y + wv.z * v3.z + wv.w * v3.w;
            }
            S.s_g[0][t] = acc0;
            S.s_g[1][t] = acc1;
            S.s_g[2][t] = acc2;
            S.s_g[3][t] = acc3;
        }
        __syncthreads();
        {
            const int gi = t >> 6, k = t & 63;
            float gc = sigmoidf_(S.s_g[gi][k]);
            float gf = sigmoidf_(S.s_g[gi][64 + k]);
            float gg = tanhf(S.s_g[gi][128 + k]);
            float go = sigmoidf_(S.s_g[gi][192 + k]);
            float cc = gf * S.s_c[gi][k] + gc * gg;
            S.s_c[gi][k] = cc;
            S.s_act[gi][k] = go * tanhf(cc);       // h (== q)
        }
        __syncthreads();

        // ---- attention per graph: pipelined streaming pass, online softmax ----
        for (int gi = 0; gi < ngr; gi++) {
            const float4 q0 = ((const float4*)S.s_act[gi])[4 * ql];
            const float4 q1 = ((const float4*)S.s_act[gi])[4 * ql + 1];
            const float4 q2 = ((const float4*)S.s_act[gi])[4 * ql + 2];
            const float4 q3 = ((const float4*)S.s_act[gi])[4 * ql + 3];
            float m = -FLT_MAX, s = 0.0f;
            float4 R0 = make_float4(0.f, 0.f, 0.f, 0.f);
            float4 R1 = R0, R2 = R0, R3 = R0;

            if (step == 0)
                attn_pass<true >(x, wstage, row0[gi], row1[gi], w, lane, q, ql,
                                 q0, q1, q2, q3, m, s, R0, R1, R2, R3);
            else
                attn_pass<false>(x, wstage, row0[gi], row1[gi], w, lane, q, ql,
                                 q0, q1, q2, q3, m, s, R0, R1, R2, R3);

            // combine 64 quad partials
            if (ql == 0) { S.s_rm[qd] = m; S.s_rs[qd] = s; }
            ((float4*)S.s_rR[qd])[4 * ql]     = R0;
            ((float4*)S.s_rR[qd])[4 * ql + 1] = R1;
            ((float4*)S.s_rR[qd])[4 * ql + 2] = R2;
            ((float4*)S.s_rR[qd])[4 * ql + 3] = R3;
            __syncthreads();
            if (t < 64) {
                float M = -FLT_MAX;
                #pragma unroll 16
                for (int p = 0; p < 64; p++) M = fmaxf(M, S.s_rm[p]);
                float st = 0.0f, Rk = 0.0f;
                #pragma unroll 16
                for (int p = 0; p < 64; p++) {
                    float wq = __expf(S.s_rm[p] - M);
                    st += wq * S.s_rs[p];
                    Rk += wq * S.s_rR[p][t];
                }
                S.s_act[gi][64 + t] = Rk / fmaxf(st, 1e-16f);   // r
            }
            __syncthreads();
        }
    }

    // ---- final MLP per graph: 128 -> 256 (relu) -> 128 ----
    for (int gi = 0; gi < ngr; gi++) {
        {
            float acc = b1[t];
            const float4* a = (const float4*)S.s_act[gi];
            #pragma unroll 8
            for (int k4 = 0; k4 < 32; k4++) {
                float4 wv = d_W1p[k4 * 256 + t];
                float4 v  = a[k4];
                acc += wv.x * v.x + wv.y * v.y + wv.z * v.z + wv.w * v.w;
            }
            S.s_g[0][t] = fmaxf(acc, 0.0f);
        }
        __syncthreads();
        if (t < 128) {
            float acc = b2[t];
            const float4* hv = (const float4*)S.s_g[0];
            #pragma unroll 8
            for (int k4 = 0; k4 < 64; k4++) {
                float4 wv = d_W2p[k4 * 128 + t];
                float4 v  = hv[k4];
                acc += wv.x * v.x + wv.y * v.y + wv.z * v.z + wv.w * v.w;
            }
            out[(size_t)(g0 + gi) * 128 + t] = acc;
        }
        __syncthreads();
    }
}

extern "C" void kernel_launch(void* const* d_in, const int* in_sizes, int n_in,
                              void* d_out, int out_size) {
    const float* x     = (const float*)d_in[0];
    const int*   batch = (const int*)d_in[1];     // int32 (JAX x64 disabled)
    const float* Wih   = (const float*)d_in[2];
    const float* Whh   = (const float*)d_in[3];
    const float* bih   = (const float*)d_in[4];
    const float* bhh   = (const float*)d_in[5];
    const float* W1    = (const float*)d_in[6];
    const float* b1    = (const float*)d_in[7];
    const float* W2    = (const float*)d_in[8];
    const float* b2    = (const float*)d_in[9];

    int n = in_sizes[0] / HDIM;   // number of nodes

    static_assert(sizeof(Smem) <= 96 * 1024, "smem too big for occ 2");
    cudaFuncSetAttribute(fused_kernel, cudaFuncAttributeMaxDynamicSharedMemorySize,
                         (int)sizeof(Smem));

    prep_kernel<<<(n + 511) / 512, 512>>>(batch, n, Wih, Whh, bih, bhh, W1, W2);
    fused_kernel<<<CTAS, 256, sizeof(Smem)>>>(x, b1, b2, (float*)d_out, n);
}

// round 9
// speedup vs baseline: 1.5050x; 1.0552x over previous
#include <cuda_runtime.h>
#include <cuda_fp16.h>
#include <cuda_pipeline.h>
#include <cstdint>
#include <float.h>

#define NGRAPH 1024
#define HDIM   64
#define NMAX   1000000
#define CTAS   296        // 2 x 148 SMs -> one balanced wave at occ 2

// ---------------- device scratch (no allocation allowed) ----------------
__device__ float4 d_WL[32 * 256];    // packed LSTM weights: K=128 (h folded), [k4][n]
__device__ float  d_bsum[256];       // b_ih + b_hh
__device__ float4 d_W1p[32 * 256];   // W1 packed [k4][n]
__device__ float4 d_W2p[64 * 128];   // W2 packed [k4][n]
__device__ int    d_seg[NGRAPH + 1]; // segment row offsets
__device__ uint4  d_xh[NMAX * 8];    // fp16 copy of x (row = 64 halves = 8 uint4)

// dynamic shared memory layout
struct Smem {
    char  stage[8][6144];   // per-warp staging ring: fp32 3x2048B, fp16 6x1024B
    float s_act[4][128];    // per graph slot: [h(64) | r(64)]
    float s_c[4][64];
    float s_g[4][256];      // gates; s_g[0] reused as MLP hidden
    float s_rm[64];
    float s_rs[64];
    float s_rmn[64];        // per-quad max row-norm^2 partials (step 0)
    float s_mn[4];          // per graph max row-norm^2
    float s_M[4];           // per graph fixed softmax shift for this step
    float s_rR[64][64];
};

// ---------------- prep: segment offsets + weight packing ----------------
__global__ void prep_kernel(const int* __restrict__ batch, int n,
                            const float* __restrict__ Wih, const float* __restrict__ Whh,
                            const float* __restrict__ bih, const float* __restrict__ bhh,
                            const float* __restrict__ W1,  const float* __restrict__ W2) {
    int t = blockIdx.x * blockDim.x + threadIdx.x;
    if (t < n) {
        int b = batch[t];
        b = min(max(b, 0), NGRAPH - 1);
        int bp;
        if (t == 0) bp = -1;
        else {
            bp = batch[t - 1];
            bp = min(max(bp, 0), NGRAPH - 1);
        }
        for (int v = bp + 1; v <= b; v++) d_seg[v] = t;
        if (t == n - 1) {
            for (int v = b + 1; v <= NGRAPH; v++) d_seg[v] = n;
        }
    }
    // gates = h @ (W_ih[:, :64] + W_hh).T + r @ W_ih[:, 64:].T + (b_ih + b_hh)
    if (t < 32 * 256) {
        int k4 = t >> 8, nn = t & 255;
        float4 w; float* wp = (float*)&w;
        #pragma unroll
        for (int j = 0; j < 4; j++) {
            int k = k4 * 4 + j;
            if (k < 64) wp[j] = Wih[nn * 128 + k] + Whh[nn * 64 + k];
            else        wp[j] = Wih[nn * 128 + k];
        }
        d_WL[t] = w;
        float4 w1; float* w1p = (float*)&w1;
        #pragma unroll
        for (int j = 0; j < 4; j++) w1p[j] = W1[nn * 128 + k4 * 4 + j];
        d_W1p[t] = w1;
    }
    if (t < 256) d_bsum[t] = bih[t] + bhh[t];
    if (t < 64 * 128) {
        int k4 = t >> 7, nn = t & 127;
        float4 w; float* wp = (float*)&w;
        #pragma unroll
        for (int j = 0; j < 4; j++) wp[j] = W2[nn * 256 + k4 * 4 + j];
        d_W2p[t] = w;
    }
}

__device__ __forceinline__ float sigmoidf_(float v) {
    return 1.0f / (1.0f + __expf(-v));
}

// fill one 8-row slice into a staging slot via cp.async
template<bool FIRST>
__device__ __forceinline__ void fill_slice(char* slot, const float* __restrict__ x,
                                           int srow0, int r1, int lane) {
    int row = srow0 + (lane >> 2);
    row = min(row, r1 - 1);              // clamp: real data for tail rows (guarded later)
    if (FIRST) {
        const char* g = (const char*)(x + (size_t)row * HDIM) + (lane & 3) * 64;
        char* sdst = slot + (lane >> 2) * 256 + (lane & 3) * 64;
        #pragma unroll
        for (int u = 0; u < 4; u++)
            __pipeline_memcpy_async(sdst + u * 16, g + u * 16, 16);
    } else {
        const char* g = (const char*)(&d_xh[(size_t)row * 8]) + (lane & 3) * 32;
        char* sdst = slot + (lane >> 2) * 128 + (lane & 3) * 32;
        #pragma unroll
        for (int u = 0; u < 2; u++)
            __pipeline_memcpy_async(sdst + u * 16, g + u * 16, 16);
    }
}

// step-0 consumer: online softmax + max row-norm^2 tracking + fp16 copy store
__device__ __forceinline__ void consume_row_first(const char* slot, int row, int r1,
        int q, int ql,
        const float4& q0, const float4& q1, const float4& q2, const float4& q3,
        float& m, float& s, float& mn,
        float4& R0, float4& R1, float4& R2, float4& R3) {
    const bool act = (row < r1);
    const float4* p4 = (const float4*)(slot + q * 256 + ql * 64);
    float4 v0 = p4[0], v1 = p4[1], v2 = p4[2], v3 = p4[3];
    if (act) {   // fp16 copy for steps 1-4
        union { uint4 u; __half2 h[4]; } pk0, pk1;
        pk0.h[0] = __floats2half2_rn(v0.x, v0.y);
        pk0.h[1] = __floats2half2_rn(v0.z, v0.w);
        pk0.h[2] = __floats2half2_rn(v1.x, v1.y);
        pk0.h[3] = __floats2half2_rn(v1.z, v1.w);
        pk1.h[0] = __floats2half2_rn(v2.x, v2.y);
        pk1.h[1] = __floats2half2_rn(v2.z, v2.w);
        pk1.h[2] = __floats2half2_rn(v3.x, v3.y);
        pk1.h[3] = __floats2half2_rn(v3.z, v3.w);
        __stcs(&d_xh[(size_t)row * 8 + 2 * ql],     pk0.u);
        __stcs(&d_xh[(size_t)row * 8 + 2 * ql + 1], pk1.u);
    }
    float p = v0.x * q0.x + v0.y * q0.y + v0.z * q0.z + v0.w * q0.w
            + v1.x * q1.x + v1.y * q1.y + v1.z * q1.z + v1.w * q1.w
            + v2.x * q2.x + v2.y * q2.y + v2.z * q2.z + v2.w * q2.w
            + v3.x * q3.x + v3.y * q3.y + v3.z * q3.z + v3.w * q3.w;
    float n2 = v0.x * v0.x + v0.y * v0.y + v0.z * v0.z + v0.w * v0.w
             + v1.x * v1.x + v1.y * v1.y + v1.z * v1.z + v1.w * v1.w
             + v2.x * v2.x + v2.y * v2.y + v2.z * v2.z + v2.w * v2.w
             + v3.x * v3.x + v3.y * v3.y + v3.z * v3.z + v3.w * v3.w;
    p  += __shfl_xor_sync(0xffffffffu, p, 1);
    n2 += __shfl_xor_sync(0xffffffffu, n2, 1);
    p  += __shfl_xor_sync(0xffffffffu, p, 2);
    n2 += __shfl_xor_sync(0xffffffffu, n2, 2);
    if (act) {
        mn = fmaxf(mn, n2);
        if (p > m) {
            float sc = __expf(m - p);
            s *= sc;
            R0.x *= sc; R0.y *= sc; R0.z *= sc; R0.w *= sc;
            R1.x *= sc; R1.y *= sc; R1.z *= sc; R1.w *= sc;
            R2.x *= sc; R2.y *= sc; R2.z *= sc; R2.w *= sc;
            R3.x *= sc; R3.y *= sc; R3.z *= sc; R3.w *= sc;
            m = p;
        }
        float d = __expf(p - m);
        s += d;
        R0.x += d * v0.x; R0.y += d * v0.y; R0.z += d * v0.z; R0.w += d * v0.w;
        R1.x += d * v1.x; R1.y += d * v1.y; R1.z += d * v1.z; R1.w += d * v1.w;
        R2.x += d * v2.x; R2.y += d * v2.y; R2.z += d * v2.z; R2.w += d * v2.w;
        R3.x += d * v3.x; R3.y += d * v3.y; R3.z += d * v3.z; R3.w += d * v3.w;
    }
}

// steps 1-4 consumer: FIXED shift M -> straight-line, no carried compare chain
__device__ __forceinline__ void consume_row_fixed(const char* slot, int row, int r1,
        int q, int ql, float M,
        const float4& q0, const float4& q1, const float4& q2, const float4& q3,
        float& s, float4& R0, float4& R1, float4& R2, float4& R3) {
    const uint4* p4 = (const uint4*)(slot + q * 128 + ql * 32);
    union { uint4 u; __half2 h[4]; } pk0, pk1;
    pk0.u = p4[0];
    pk1.u = p4[1];
    float2 f;
    float4 v0, v1, v2, v3;
    f = __half22float2(pk0.h[0]); v0.x = f.x; v0.y = f.y;
    f = __half22float2(pk0.h[1]); v0.z = f.x; v0.w = f.y;
    f = __half22float2(pk0.h[2]); v1.x = f.x; v1.y = f.y;
    f = __half22float2(pk0.h[3]); v1.z = f.x; v1.w = f.y;
    f = __half22float2(pk1.h[0]); v2.x = f.x; v2.y = f.y;
    f = __half22float2(pk1.h[1]); v2.z = f.x; v2.w = f.y;
    f = __half22float2(pk1.h[2]); v3.x = f.x; v3.y = f.y;
    f = __half22float2(pk1.h[3]); v3.z = f.x; v3.w = f.y;
    float p = v0.x * q0.x + v0.y * q0.y + v0.z * q0.z + v0.w * q0.w
            + v1.x * q1.x + v1.y * q1.y + v1.z * q1.z + v1.w * q1.w
            + v2.x * q2.x + v2.y * q2.y + v2.z * q2.z + v2.w * q2.w
            + v3.x * q3.x + v3.y * q3.y + v3.z * q3.z + v3.w * q3.w;
    p += __shfl_xor_sync(0xffffffffu, p, 1);
    p += __shfl_xor_sync(0xffffffffu, p, 2);
    float d = (row < r1) ? __expf(p - M) : 0.0f;
    s += d;
    R0.x += d * v0.x; R0.y += d * v0.y; R0.z += d * v0.z; R0.w += d * v0.w;
    R1.x += d * v1.x; R1.y += d * v1.y; R1.z += d * v1.z; R1.w += d * v1.w;
    R2.x += d * v2.x; R2.y += d * v2.y; R2.z += d * v2.z; R2.w += d * v2.w;
    R3.x += d * v3.x; R3.y += d * v3.y; R3.z += d * v3.z; R3.w += d * v3.w;
}

// per-warp streaming attention pass with cp.async ring (no block syncs inside)
template<bool FIRST>
__device__ __forceinline__ void attn_pass(const float* __restrict__ x, char* wstage,
        int r0, int r1, int w, int lane, int q, int ql, float M,
        const float4& q0, const float4& q1, const float4& q2, const float4& q3,
        float& m, float& s, float& mn,
        float4& R0, float4& R1, float4& R2, float4& R3) {
    constexpr int S     = FIRST ? 3 : 6;
    constexpr int SLICE = FIRST ? 2048 : 1024;
    const int wrow0 = r0 + w * 8;
    const int iters = (r1 > wrow0) ? ((r1 - wrow0 + 63) >> 6) : 0;
    #pragma unroll
    for (int j = 0; j < S - 1; j++) {
        if (j < iters) fill_slice<FIRST>(wstage + j * SLICE, x, wrow0 + j * 64, r1, lane);
        __pipeline_commit();
    }
    int slot = 0;
    for (int j = 0; j < iters; j++) {
        __pipeline_wait_prior(S - 2);
        // issue next fill BEFORE the compute chain (target slot consumed 1 iter ago)
        int jn = j + S - 1;
        int sn = slot + S - 1; if (sn >= S) sn -= S;
        if (jn < iters) fill_slice<FIRST>(wstage + sn * SLICE, x, wrow0 + jn * 64, r1, lane);
        __pipeline_commit();
        if (FIRST)
            consume_row_first(wstage + slot * SLICE, wrow0 + j * 64 + q, r1, q, ql,
                              q0, q1, q2, q3, m, s, mn, R0, R1, R2, R3);
        else
            consume_row_fixed(wstage + slot * SLICE, wrow0 + j * 64 + q, r1, q, ql, M,
                              q0, q1, q2, q3, s, R0, R1, R2, R3);
        __syncwarp();            // all lanes done reading slot before it is refilled
        slot++; if (slot == S) slot = 0;
    }
}

// ---------------- fused Set2Set + MLP: 296 CTAs, dynamic graph partition ----------------
__global__ __launch_bounds__(256, 2)
void fused_kernel(const float* __restrict__ x,
                  const float* __restrict__ b1,
                  const float* __restrict__ b2,
                  float* __restrict__ out, int n) {
    extern __shared__ char smraw[];
    Smem& S = *(Smem*)smraw;

    const int t    = threadIdx.x;
    const int c    = blockIdx.x;
    const int w    = t >> 5;          // warp 0..7
    const int lane = t & 31;
    const int q    = lane >> 2;       // quad within warp 0..7
    const int ql   = t & 3;           // lane within quad
    const int qd   = t >> 2;          // global quad 0..63
    char* wstage   = S.stage[w];

    const int g0  = (c * NGRAPH) / CTAS;
    const int g1  = ((c + 1) * NGRAPH) / CTAS;
    const int ngr = g1 - g0;          // 3 or 4

    if (t < 128) {
        #pragma unroll
        for (int gi = 0; gi < 4; gi++) {
            S.s_act[gi][t] = 0.0f;
            if (t < 64) S.s_c[gi][t] = 0.0f;
        }
    }
    if (t < 4) { S.s_mn[t] = 0.0f; S.s_M[t] = 0.0f; }
    int row0[4], row1[4];
    #pragma unroll
    for (int gi = 0; gi < 4; gi++) {
        int gg = min(g0 + gi, NGRAPH - 1);
        int a = d_seg[gg];
        int b = d_seg[gg + 1];
        a = min(max(a, 0), n);
        b = min(max(b, a), n);
        row0[gi] = a;
        row1[gi] = b;
    }
    __syncthreads();

    for (int step = 0; step < 5; step++) {
        // ---- LSTM gates: 256 threads = 256 gates, all graph slots per thread ----
        {
            float acc0 = d_bsum[t], acc1 = acc0, acc2 = acc0, acc3 = acc0;
            const float4* a0 = (const float4*)S.s_act[0];
            const float4* a1 = (const float4*)S.s_act[1];
            const float4* a2 = (const float4*)S.s_act[2];
            const float4* a3 = (const float4*)S.s_act[3];
            #pragma unroll 8
            for (int k4 = 0; k4 < 32; k4++) {
                float4 wv = d_WL[k4 * 256 + t];
                float4 v0 = a0[k4];
                float4 v1 = a1[k4];
                float4 v2 = a2[k4];
                float4 v3 = a3[k4];
                acc0 += wv.x * v0.x + wv.y * v0.y + wv.z * v0.z + wv.w * v0.w;
                acc1 += wv.x * v1.x + wv.y * v1.y + wv.z * v1.z + wv.w * v1.w;
                acc2 += wv.x * v2.x + wv.y * v2.y + wv.z * v2.z + wv.w * v2.w;
                acc3 += wv.x * v3.x + wv.y * v3.y + wv.z * v3.z + wv.w * v3.w;
            }
            S.s_g[0][t] = acc0;
            S.s_g[1][t] = acc1;
            S.s_g[2][t] = acc2;
            S.s_g[3][t] = acc3;
        }
        __syncthreads();
        {
            const int gi = t >> 6, k = t & 63;
            float gc = sigmoidf_(S.s_g[gi][k]);
            float gf = sigmoidf_(S.s_g[gi][64 + k]);
            float gg = tanhf(S.s_g[gi][128 + k]);
            float go = sigmoidf_(S.s_g[gi][192 + k]);
            float cc = gf * S.s_c[gi][k] + gc * gg;
            S.s_c[gi][k] = cc;
            S.s_act[gi][k] = go * tanhf(cc);       // h (== q)
        }
        __syncthreads();
        if (step > 0) {
            // fixed shift for this step: M = ||q|| * sqrt(max row-norm^2)
            if (t < 4) {
                float q2 = 0.0f;
                #pragma unroll 16
                for (int k = 0; k < 64; k++) {
                    float hv = S.s_act[t][k];
                    q2 += hv * hv;
                }
                S.s_M[t] = sqrtf(q2 * S.s_mn[t]);
            }
            __syncthreads();
        }

        // ---- attention per graph: pipelined streaming pass ----
        for (int gi = 0; gi < ngr; gi++) {
            const float4 q0 = ((const float4*)S.s_act[gi])[4 * ql];
            const float4 q1 = ((const float4*)S.s_act[gi])[4 * ql + 1];
            const float4 q2 = ((const float4*)S.s_act[gi])[4 * ql + 2];
            const float4 q3 = ((const float4*)S.s_act[gi])[4 * ql + 3];
            const float M = S.s_M[gi];
            float m = -FLT_MAX, s = 0.0f, mn = 0.0f;
            float4 R0 = make_float4(0.f, 0.f, 0.f, 0.f);
            float4 R1 = R0, R2 = R0, R3 = R0;

            if (step == 0)
                attn_pass<true >(x, wstage, row0[gi], row1[gi], w, lane, q, ql, M,
                                 q0, q1, q2, q3, m, s, mn, R0, R1, R2, R3);
            else
                attn_pass<false>(x, wstage, row0[gi], row1[gi], w, lane, q, ql, M,
                                 q0, q1, q2, q3, m, s, mn, R0, R1, R2, R3);

            // combine 64 quad partials
            if (ql == 0) {
                S.s_rm[qd]  = (step == 0) ? m : M;
                S.s_rs[qd]  = s;
                S.s_rmn[qd] = mn;
            }
            ((float4*)S.s_rR[qd])[4 * ql]     = R0;
            ((float4*)S.s_rR[qd])[4 * ql + 1] = R1;
            ((float4*)S.s_rR[qd])[4 * ql + 2] = R2;
            ((float4*)S.s_rR[qd])[4 * ql + 3] = R3;
            __syncthreads();
            if (t < 64) {
                float Mx = -FLT_MAX;
                #pragma unroll 16
                for (int p = 0; p < 64; p++) Mx = fmaxf(Mx, S.s_rm[p]);
                float st = 0.0f, Rk = 0.0f;
                #pragma unroll 16
                for (int p = 0; p < 64; p++) {
                    float wq = __expf(S.s_rm[p] - Mx);
                    st += wq * S.s_rs[p];
                    Rk += wq * S.s_rR[p][t];
                }
                S.s_act[gi][64 + t] = Rk / fmaxf(st, 1e-16f);   // r
                if (step == 0 && t == 0) {
                    float mnx = 0.0f;
                    #pragma unroll 16
                    for (int p = 0; p < 64; p++) mnx = fmaxf(mnx, S.s_rmn[p]);
                    S.s_mn[gi] = mnx;
                }
            }
            __syncthreads();
        }
    }

    // ---- final MLP per graph: 128 -> 256 (relu) -> 128 ----
    for (int gi = 0; gi < ngr; gi++) {
        {
            float acc = b1[t];
            const float4* a = (const float4*)S.s_act[gi];
            #pragma unroll 8
            for (int k4 = 0; k4 < 32; k4++) {
                float4 wv = d_W1p[k4 * 256 + t];
                float4 v  = a[k4];
                acc += wv.x * v.x + wv.y * v.y + wv.z * v.z + wv.w * v.w;
            }
            S.s_g[0][t] = fmaxf(acc, 0.0f);
        }
        __syncthreads();
        if (t < 128) {
            float acc = b2[t];
            const float4* hv = (const float4*)S.s_g[0];
            #pragma unroll 8
            for (int k4 = 0; k4 < 64; k4++) {
                float4 wv = d_W2p[k4 * 128 + t];
                float4 v  = hv[k4];
                acc += wv.x * v.x + wv.y * v.y + wv.z * v.z + wv.w * v.w;
            }
            out[(size_t)(g0 + gi) * 128 + t] = acc;
        }
        __syncthreads();
    }
}

extern "C" void kernel_launch(void* const* d_in, const int* in_sizes, int n_in,
                              void* d_out, int out_size) {
    const float* x     = (const float*)d_in[0];
    const int*   batch = (const int*)d_in[1];     // int32 (JAX x64 disabled)
    const float* Wih   = (const float*)d_in[2];
    const float* Whh   = (const float*)d_in[3];
    const float* bih   = (const float*)d_in[4];
    const float* bhh   = (const float*)d_in[5];
    const float* W1    = (const float*)d_in[6];
    const float* b1    = (const float*)d_in[7];
    const float* W2    = (const float*)d_in[8];
    const float* b2    = (const float*)d_in[9];

    int n = in_sizes[0] / HDIM;   // number of nodes

    static_assert(sizeof(Smem) <= 96 * 1024, "smem too big for occ 2");
    cudaFuncSetAttribute(fused_kernel, cudaFuncAttributeMaxDynamicSharedMemorySize,
                         (int)sizeof(Smem));

    prep_kernel<<<(n + 511) / 512, 512>>>(batch, n, Wih, Whh, bih, bhh, W1, W2);
    fused_kernel<<<CTAS, 256, sizeof(Smem)>>>(x, b1, b2, (float*)d_out, n);
}